// round 13
// baseline (speedup 1.0000x reference)
#include <cuda_runtime.h>
#include <cuda_fp16.h>
#include <cstdint>

#define TS 47

// ---------------- fp32 scratch ----------------
__device__ __align__(128) float g_featw1 [8192 * 512];
__device__ __align__(128) float g_features[8192 * 256];
__device__ __align__(128) float g_embmx  [6016 * 1536];
__device__ __align__(128) float g_hidw2  [128 * 512];

// ---------------- fp16 planes ----------------
__device__ __align__(128) __half g_img_hi [8192 * 2048], g_img_lo [8192 * 2048];
__device__ __align__(128) __half g_feat_hi[8192 * 256],  g_feat_lo[8192 * 256];
__device__ __align__(128) __half g_etok_hi[6016 * 256],  g_etok_lo[6016 * 256];
__device__ __align__(128) __half g_st_hi  [6016 * 512],  g_st_lo  [6016 * 512];
__device__ __align__(128) __half g_f1o_hi [6016 * 512],  g_f1o_lo [6016 * 512];
__device__ __align__(128) __half g_ctx_hi [128 * 256],   g_ctx_lo [128 * 256];
__device__ __align__(128) __half g_wfc_h [2048 * 256];
__device__ __align__(128) __half g_w1_h  [256 * 512];
__device__ __align__(128) __half g_gk1_h [256 * 1536];
__device__ __align__(128) __half g_gk2_h [256 * 1536];
__device__ __align__(128) __half g_w2_h  [512 * 512];
__device__ __align__(128) __half g_f1w_h [512 * 512];
__device__ __align__(128) __half g_f2w_h [512 * 5000];

// ---------------- barrier state (monotonic, replay-safe) ----------------
__device__ unsigned g_flags[128];
__device__ unsigned g_epoch;

// ---------------- helpers ----------------
__device__ __forceinline__ float tanh_apx(float x) {
    float y;
    asm("tanh.approx.f32 %0, %1;" : "=f"(y) : "f"(x));
    return y;
}
__device__ __forceinline__ unsigned ld_acq(const unsigned* p) {
    unsigned v;
    asm volatile("ld.acquire.gpu.global.u32 %0, [%1];" : "=r"(v) : "l"(p));
    return v;
}
__device__ __forceinline__ void st_rel(unsigned* p, unsigned v) {
    asm volatile("st.release.gpu.global.u32 [%0], %1;" :: "l"(p), "r"(v) : "memory");
}
// one-hop barrier: every block publishes its flag, all blocks poll all flags
__device__ __forceinline__ void grid_bar3(int bid, int tid, unsigned tgt) {
    __syncthreads();
    if (tid == 0) st_rel(&g_flags[bid], tgt);
    if (tid < 128) {
        while ((int)(ld_acq(&g_flags[tid]) - tgt) < 0) { }
    }
    __syncthreads();
}
__device__ __forceinline__ uint32_t smem_u32(const void* p) {
    uint32_t a;
    asm("{ .reg .u64 t; cvta.to.shared.u64 t, %1; cvt.u32.u64 %0, t; }"
        : "=r"(a) : "l"(p));
    return a;
}
__device__ __forceinline__ void ldsm_x4(uint32_t* r, uint32_t addr) {
    asm volatile("ldmatrix.sync.aligned.m8n8.x4.shared.b16 {%0,%1,%2,%3}, [%4];"
        : "=r"(r[0]), "=r"(r[1]), "=r"(r[2]), "=r"(r[3]) : "r"(addr));
}
__device__ __forceinline__ void ldsm_x2t(uint32_t* r, uint32_t addr) {
    asm volatile("ldmatrix.sync.aligned.m8n8.x2.trans.shared.b16 {%0,%1}, [%2];"
        : "=r"(r[0]), "=r"(r[1]) : "r"(addr));
}
__device__ __forceinline__ void mma_f16(float* c, const uint32_t* a, const uint32_t* b) {
    asm volatile("mma.sync.aligned.m16n8k16.row.col.f32.f16.f16.f32 "
        "{%0,%1,%2,%3},{%4,%5,%6,%7},{%8,%9},{%0,%1,%2,%3};"
        : "+f"(c[0]), "+f"(c[1]), "+f"(c[2]), "+f"(c[3])
        : "r"(a[0]), "r"(a[1]), "r"(a[2]), "r"(a[3]), "r"(b[0]), "r"(b[1]));
}
__device__ __forceinline__ uint32_t packh(__half a, __half b) {
    __half2 t = __halves2half2(a, b);
    return *(uint32_t*)&t;
}
__device__ __forceinline__ void cpasync16(uint32_t sa, const void* ga, int sz) {
    asm volatile("cp.async.cg.shared.global [%0], [%1], 16, %2;"
                 :: "r"(sa), "l"(ga), "r"(sz) : "memory");
}
#define CP_COMMIT() asm volatile("cp.async.commit_group;" ::: "memory")

// ---------------- fused fp32 -> fp16 converts (ONE launch) ----------------
__global__ void cvt_fused(const float* __restrict__ img, const float* __restrict__ W_fc,
                          const float* __restrict__ W1, const float* __restrict__ gru_k,
                          const float* __restrict__ fc1_w, const float* __restrict__ fc2_w,
                          const float* __restrict__ W2)
{
    int blk = blockIdx.x;
    const float* src;
    __half *hi = nullptr, *lo = nullptr, *one = nullptr;
    int base;
    if (blk < 16384)      { src = img;              hi = g_img_hi; lo = g_img_lo; base = blk; }
    else if (blk < 16896) { src = W_fc;             one = g_wfc_h; base = blk - 16384; }
    else if (blk < 17024) { src = W1;               one = g_w1_h;  base = blk - 16896; }
    else if (blk < 17408) { src = gru_k + 256*1536; one = g_gk2_h; base = blk - 17024; }
    else if (blk < 17664) { src = fc1_w;            one = g_f1w_h; base = blk - 17408; }
    else if (blk < 20164) { src = fc2_w;            one = g_f2w_h; base = blk - 17664; }
    else if (blk < 20420) { src = W2;               one = g_w2_h;  base = blk - 20164; }
    else                  { src = gru_k;            one = g_gk1_h; base = blk - 20420; }
    int i = (base * 256 + threadIdx.x) * 4;
    float4 v = *(const float4*)(src + i);
    __half hx = __float2half(v.x), hy = __float2half(v.y);
    __half hz = __float2half(v.z), hw = __float2half(v.w);
    if (one) {
        *(uint2*)(one + i) = make_uint2(packh(hx, hy), packh(hz, hw));
    } else {
        *(uint2*)(hi + i) = make_uint2(packh(hx, hy), packh(hz, hw));
        __half lx = __float2half(v.x - __half2float(hx));
        __half ly = __float2half(v.y - __half2float(hy));
        __half lz = __float2half(v.z - __half2float(hz));
        __half lw = __float2half(v.w - __half2float(hw));
        *(uint2*)(lo + i) = make_uint2(packh(lx, ly), packh(lz, lw));
    }
}

// ---------------- fp16 2-term tensor-core GEMM, 3-stage cp.async pipeline ----------------
#define OFF_ALO 10240
#define OFF_B   20480
#define STAGE   29184

__global__ void __launch_bounds__(256, 2) mma_gemm_hf(
    const __half* __restrict__ Ahi, const __half* __restrict__ Alo,
    const __half* __restrict__ B,
    const float* __restrict__ bias, float* __restrict__ C,
    __half* __restrict__ Chi, __half* __restrict__ Clo,
    int M, int N, int K, int relu, int remap)
{
    extern __shared__ char smem[];
    const int tid = threadIdx.x;
    const int wid = tid >> 5, lane = tid & 31;
    const int bm = blockIdx.y * 128, bn = blockIdx.x * 128;
    const int wm = (wid >> 2) * 64;
    const int wn = (wid & 3) * 32;
    const uint32_t sbase = smem_u32(smem);

    float acc[4][4][4] = {};
    const int nc = K >> 5;

    auto issue = [&](int c) {
        int k0 = c << 5;
        uint32_t sb = sbase + (c % 3) * STAGE;
        #pragma unroll
        for (int i = 0; i < 2; i++) {
            int task = tid + (i << 8);
            int m = task >> 2, k8 = (task & 3) << 3;
            uint32_t sa = sb + m * 80 + (k8 << 1);
            size_t go = (size_t)(bm + m) * K + k0 + k8;
            cpasync16(sa, Ahi + go, 16);
            cpasync16(sa + OFF_ALO, Alo + go, 16);
        }
        #pragma unroll
        for (int i = 0; i < 2; i++) {
            int task = tid + (i << 8);
            int kk = task >> 4, n8 = (task & 15) << 3;
            int gc = bn + n8;
            uint32_t sa = sb + OFF_B + kk * 272 + (n8 << 1);
            size_t go = (size_t)(k0 + kk) * N + gc;
            int sz = (gc + 8 <= N) ? 16 : 0;
            cpasync16(sa, B + go, sz);
        }
        CP_COMMIT();
    };

    issue(0);
    if (nc > 1) issue(1);

    for (int c = 0; c < nc; c++) {
        if (c + 2 < nc) {
            issue(c + 2);
            asm volatile("cp.async.wait_group 2;" ::: "memory");
        } else if (c + 1 < nc) {
            asm volatile("cp.async.wait_group 1;" ::: "memory");
        } else {
            asm volatile("cp.async.wait_group 0;" ::: "memory");
        }
        __syncthreads();

        uint32_t base = sbase + (c % 3) * STAGE;
        uint32_t aAhi = base, aAlo = base + OFF_ALO;
        uint32_t aB = base + OFF_B;

        #pragma unroll
        for (int kk = 0; kk < 2; kk++) {
            int kb = kk * 16;
            uint32_t ahi[4][4], alo[4][4];
            #pragma unroll
            for (int im = 0; im < 4; im++) {
                int row = wm + im * 16 + (lane & 15);
                uint32_t off = row * 80 + kb * 2 + ((lane >> 4) << 4);
                ldsm_x4(ahi[im], aAhi + off);
                ldsm_x4(alo[im], aAlo + off);
            }
            #pragma unroll
            for (int jn = 0; jn < 4; jn++) {
                int n = wn + jn * 8;
                uint32_t off = (kb + (lane & 15)) * 272 + n * 2;
                uint32_t bb[2];
                ldsm_x2t(bb, aB + off);
                #pragma unroll
                for (int im = 0; im < 4; im++) {
                    mma_f16(acc[im][jn], ahi[im], bb);
                    mma_f16(acc[im][jn], alo[im], bb);
                }
            }
        }
        __syncthreads();
    }

    int tr = lane >> 2, tc = (lane & 3) << 1;
    #pragma unroll
    for (int im = 0; im < 4; im++) {
        #pragma unroll
        for (int half = 0; half < 2; half++) {
            int grow = bm + wm + im * 16 + tr + half * 8;
            size_t ro;
            if (remap) {
                int t = grow >> 7, b = grow & 127;
                ro = ((size_t)b * TS + t) * (size_t)N;
            } else {
                ro = (size_t)grow * (size_t)N;
            }
            #pragma unroll
            for (int jn = 0; jn < 4; jn++) {
                int gc = bn + wn + jn * 8 + tc;
                if (gc < N) {
                    float v0 = acc[im][jn][half * 2 + 0] + bias[gc];
                    float v1 = acc[im][jn][half * 2 + 1] + bias[gc + 1];
                    if (relu) { v0 = fmaxf(v0, 0.f); v1 = fmaxf(v1, 0.f); }
                    if (C) *(float2*)(C + ro + gc) = make_float2(v0, v1);
                    if (Chi) {
                        __half h0 = __float2half(v0);
                        __half h1 = __float2half(v1);
                        *(uint32_t*)(Chi + ro + gc) = packh(h0, h1);
                        __half l0 = __float2half(v0 - __half2float(h0));
                        __half l1 = __float2half(v1 - __half2float(h1));
                        *(uint32_t*)(Clo + ro + gc) = packh(l0, l1);
                    }
                }
            }
        }
    }
}

// ---------------- token embedding gather -> fp16 pair ----------------
__global__ void gather_kernel(const int* __restrict__ target,
                              const float* __restrict__ emb)
{
    int row = blockIdx.x;
    int e = threadIdx.x;
    int t = row >> 7, b = row & 127;
    int tok = (t == 0) ? 1 : target[b * 48 + t];
    float v = emb[(size_t)tok * 256 + e];
    __half h = __float2half(v);
    g_etok_hi[(size_t)row * 256 + e] = h;
    g_etok_lo[(size_t)row * 256 + e] = __float2half(v - __half2float(h));
}

// ---------------- persistent step loop (R12 structure, one-hop barrier) ----------------
__global__ __launch_bounds__(256) void step_loop_kernel(
    const float* __restrict__ V, const float* __restrict__ bV,
    const float* __restrict__ b2, const float* __restrict__ gru_b)
{
    extern __shared__ float dsm[];
    float* sFW1  = dsm;
    float* sFEAT = dsm + 32768;
    float* work  = dsm + 49152;

    const int bid = blockIdx.x;
    const int tid = threadIdx.x;
    const int wid = tid >> 5, lane = tid & 31;
    unsigned bar = g_epoch;
    const unsigned bar0 = bar;

    for (int j = tid; j < 8192; j += 256)
        *(float4*)&sFW1[j * 4] = *(const float4*)(g_featw1 + (size_t)bid * 32768 + j * 4);
    for (int j = tid; j < 4096; j += 256)
        *(float4*)&sFEAT[j * 4] = *(const float4*)(g_features + (size_t)bid * 16384 + j * 4);
    __syncthreads();

    const uint32_t wb = smem_u32(work);

    for (int t = 0; t < TS; t++) {
        // ---- Phase A: hidw2 = states[t-1] @ W2, fp16 2-term mma (64 blocks) ----
        if (t > 0) {
            if (bid < 64) {
                int bm = (bid >> 4) * 32, bn = (bid & 15) * 32;
                const __half* Ah = g_st_hi + (size_t)(t - 1) * 65536;
                const __half* Al = g_st_lo + (size_t)(t - 1) * 65536;

                auto issueA = [&](int c) {
                    uint32_t st = wb + (c & 1) * 14336;
                    int k0 = c * 64;
                    #pragma unroll
                    for (int i = 0; i < 2; i++) {
                        int idx = tid + (i << 8);
                        int r = idx >> 4, rem = idx & 15, pl = rem >> 3, seg = rem & 7;
                        const __half* src = (pl ? Al : Ah) + (size_t)(bm + r) * 512 + k0 + seg * 8;
                        cpasync16(st + pl * 4608 + r * 144 + seg * 16, src, 16);
                    }
                    {
                        int kr = tid >> 2, seg = tid & 3;
                        cpasync16(st + 9216 + kr * 80 + seg * 16,
                                  g_w2_h + (size_t)(k0 + kr) * 512 + bn + seg * 8, 16);
                    }
                    CP_COMMIT();
                };
                issueA(0); issueA(1);

                int wmi = (wid >> 2) * 16;
                int wni = (wid & 3) * 8;
                float acc[4] = {};
                for (int c = 0; c < 8; c++) {
                    if (c < 7) asm volatile("cp.async.wait_group 1;" ::: "memory");
                    else       asm volatile("cp.async.wait_group 0;" ::: "memory");
                    __syncthreads();
                    uint32_t st = wb + (c & 1) * 14336;
                    #pragma unroll
                    for (int ks = 0; ks < 4; ks++) {
                        uint32_t ahi[4], alo[4], bb[2];
                        int row = wmi + (lane & 15);
                        uint32_t aoff = row * 144 + ks * 32 + ((lane >> 4) << 4);
                        ldsm_x4(ahi, st + aoff);
                        ldsm_x4(alo, st + 4608 + aoff);
                        uint32_t boff = 9216 + (ks * 16 + (lane & 15)) * 80 + wni * 2;
                        ldsm_x2t(bb, st + boff);
                        mma_f16(acc, ahi, bb);
                        mma_f16(acc, alo, bb);
                    }
                    __syncthreads();
                    if (c + 2 < 8) issueA(c + 2);
                }
                int tr = lane >> 2, tc2 = (lane & 3) * 2;
                int col = bn + wni + tc2;
                *(float2*)&g_hidw2[(bm + wmi + tr) * 512 + col] = make_float2(acc[0], acc[1]);
                *(float2*)&g_hidw2[(bm + wmi + tr + 8) * 512 + col] = make_float2(acc[2], acc[3]);
            }
            grid_bar3(bid, tid, ++bar);
        }

        // ---- Phase B: Bahdanau attention; emits ctx fp16 pairs ----
        {
            float* hw2 = work;
            float* sV  = work + 512;
            float* sl  = work + 1024;
            int b = bid;
            if (t > 0) {
                hw2[tid]       = g_hidw2[b * 512 + tid]       + b2[tid];
                hw2[tid + 256] = g_hidw2[b * 512 + tid + 256] + b2[tid + 256];
            } else {
                hw2[tid]       = b2[tid];
                hw2[tid + 256] = b2[tid + 256];
            }
            sV[tid]       = V[tid];
            sV[tid + 256] = V[tid + 256];
            __syncthreads();

            #pragma unroll
            for (int p = 0; p < 8; p++) {
                int l = wid * 8 + p;
                const float* row = sFW1 + l * 512;
                float a = 0.f;
                #pragma unroll
                for (int j = 0; j < 16; j++) {
                    int u = lane + j * 32;
                    float s = tanh_apx(row[u] + hw2[u]);
                    a = fmaf(s, sV[u], a);
                }
                #pragma unroll
                for (int o = 16; o; o >>= 1) a += __shfl_xor_sync(0xffffffffu, a, o);
                if (lane == 0) sl[l] = a + bV[0];
            }
            __syncthreads();

            if (tid < 32) {
                float v0 = sl[tid], v1 = sl[tid + 32];
                float m = fmaxf(v0, v1);
                #pragma unroll
                for (int o = 16; o; o >>= 1) m = fmaxf(m, __shfl_xor_sync(0xffffffffu, m, o));
                float e0 = __expf(v0 - m), e1 = __expf(v1 - m);
                float s = e0 + e1;
                #pragma unroll
                for (int o = 16; o; o >>= 1) s += __shfl_xor_sync(0xffffffffu, s, o);
                float inv = 1.0f / s;
                sl[tid] = e0 * inv;
                sl[tid + 32] = e1 * inv;
            }
            __syncthreads();

            float c = 0.f;
            #pragma unroll 8
            for (int l = 0; l < 64; l++)
                c = fmaf(sl[l], sFEAT[l * 256 + tid], c);
            __half h = __float2half(c);
            g_ctx_hi[b * 256 + tid] = h;
            g_ctx_lo[b * 256 + tid] = __float2half(c - __half2float(h));
        }
        grid_bar3(bid, tid, ++bar);

        // ---- Phase C+D: mx = ctx @ gru_k[:256] (fp16 mma) + GRU pointwise ----
        {
            int b0 = (bid >> 4) * 16;
            int u0 = (bid & 15) * 32;
            const uint32_t CTXLO = 8448, WST = 16896, WSZ = 6656;

            auto issueW = [&](int c) {
                uint32_t st = wb + WST + (c & 1) * WSZ;
                int k0 = c * 32;
                #pragma unroll
                for (int i = 0; i < 2; i++) {
                    int idx = tid + (i << 8);
                    if (idx < 384) {
                        int g = idx >> 7, rem = idx & 127, kr = rem >> 2, seg = rem & 3;
                        cpasync16(st + kr * 208 + g * 64 + seg * 16,
                                  g_gk1_h + (size_t)(k0 + kr) * 1536 + g * 512 + u0 + seg * 8, 16);
                    }
                }
            };
            {
                #pragma unroll
                for (int i = 0; i < 4; i++) {
                    int idx = tid + (i << 8);
                    int r = idx >> 6, rem = idx & 63, pl = rem >> 5, seg = rem & 31;
                    const __half* src = (pl ? g_ctx_lo : g_ctx_hi) + (size_t)(b0 + r) * 256 + seg * 8;
                    cpasync16(wb + pl * CTXLO + r * 528 + seg * 16, src, 16);
                }
                issueW(0); CP_COMMIT();
                issueW(1); CP_COMMIT();
            }

            float acc0[4] = {}, acc1[4] = {};
            int tile0 = wid, tile1 = wid + 8;

            for (int c = 0; c < 8; c++) {
                if (c < 7) asm volatile("cp.async.wait_group 1;" ::: "memory");
                else       asm volatile("cp.async.wait_group 0;" ::: "memory");
                __syncthreads();
                uint32_t st = wb + WST + (c & 1) * WSZ;
                #pragma unroll
                for (int ks = 0; ks < 2; ks++) {
                    uint32_t ahi[4], alo[4], bb[2];
                    int row = lane & 15;
                    uint32_t aoff = row * 528 + (c * 32 + ks * 16) * 2 + ((lane >> 4) << 4);
                    ldsm_x4(ahi, wb + aoff);
                    ldsm_x4(alo, wb + CTXLO + aoff);
                    {
                        int g = tile0 >> 2, ns = tile0 & 3;
                        ldsm_x2t(bb, st + (ks * 16 + (lane & 15)) * 208 + g * 64 + ns * 16);
                        mma_f16(acc0, ahi, bb);
                        mma_f16(acc0, alo, bb);
                    }
                    if (wid < 4) {
                        int g = tile1 >> 2, ns = tile1 & 3;
                        ldsm_x2t(bb, st + (ks * 16 + (lane & 15)) * 208 + g * 64 + ns * 16);
                        mma_f16(acc1, ahi, bb);
                        mma_f16(acc1, alo, bb);
                    }
                }
                __syncthreads();
                if (c + 2 < 8) { issueW(c + 2); CP_COMMIT(); }
            }

            __syncthreads();
            float* mxs = work;
            int tr = lane >> 2, tc2 = (lane & 3) * 2;
            {
                int cb = (tile0 >> 2) * 32 + (tile0 & 3) * 8 + tc2;
                mxs[tr * 104 + cb] = acc0[0];       mxs[tr * 104 + cb + 1] = acc0[1];
                mxs[(tr + 8) * 104 + cb] = acc0[2]; mxs[(tr + 8) * 104 + cb + 1] = acc0[3];
            }
            if (wid < 4) {
                int cb = (tile1 >> 2) * 32 + (tile1 & 3) * 8 + tc2;
                mxs[tr * 104 + cb] = acc1[0];       mxs[tr * 104 + cb + 1] = acc1[1];
                mxs[(tr + 8) * 104 + cb] = acc1[2]; mxs[(tr + 8) * 104 + cb + 1] = acc1[3];
            }
            __syncthreads();

            #pragma unroll
            for (int i = 0; i < 2; i++) {
                int it = tid + (i << 8);
                int ul = it & 31, b = it >> 5;
                int u = u0 + ul;
                size_t r = (size_t)t * 128 + (b0 + b);
                float xz = mxs[b * 104 + ul]      + g_embmx[r * 1536 + u];
                float xr = mxs[b * 104 + 32 + ul] + g_embmx[r * 1536 + 512 + u];
                float xh = mxs[b * 104 + 64 + ul] + g_embmx[r * 1536 + 1024 + u];
                float rz = gru_b[1536 + u];
                float rr = gru_b[2048 + u];
                float rh = gru_b[2560 + u];
                float z  = 1.f / (1.f + __expf(-(xz + rz)));
                float rg = 1.f / (1.f + __expf(-(xr + rr)));
                float hh = tanh_apx(xh + rg * rh);
                float st = (1.f - z) * hh;
                __half h = __float2half(st);
                g_st_hi[r * 512 + u] = h;
                g_st_lo[r * 512 + u] = __float2half(st - __half2float(h));
            }
        }
        grid_bar3(bid, tid, ++bar);
    }

    if (bid == 0 && tid == 0) g_epoch = bar0 + (unsigned)(3 * TS - 1);
}

// ---------------- launch ----------------
extern "C" void kernel_launch(void* const* d_in, const int* in_sizes, int n_in,
                              void* d_out, int out_size)
{
    const float* img    = (const float*)d_in[0];
    const int*   target = (const int*)  d_in[1];
    const float* W_fc   = (const float*)d_in[2];
    const float* b_fc   = (const float*)d_in[3];
    const float* W1     = (const float*)d_in[4];
    const float* b1     = (const float*)d_in[5];
    const float* W2     = (const float*)d_in[6];
    const float* b2     = (const float*)d_in[7];
    const float* V      = (const float*)d_in[8];
    const float* bV     = (const float*)d_in[9];
    const float* emb    = (const float*)d_in[10];
    const float* gru_k  = (const float*)d_in[11];
    /* d_in[12] = gru_rk : dead (zero GRU state) */
    const float* gru_b  = (const float*)d_in[13];
    const float* fc1_w  = (const float*)d_in[14];
    const float* fc1_b  = (const float*)d_in[15];
    const float* fc2_w  = (const float*)d_in[16];
    const float* fc2_b  = (const float*)d_in[17];
    float* out = (float*)d_out;

    float *featw1, *features, *embmx;
    __half *imgH, *imgL, *featH, *featL, *etH, *etL, *stH, *stL, *f1oH, *f1oL;
    __half *wfcH, *w1H, *gk2H, *f1wH, *f2wH;
    cudaGetSymbolAddress((void**)&featw1,   g_featw1);
    cudaGetSymbolAddress((void**)&features, g_features);
    cudaGetSymbolAddress((void**)&embmx,    g_embmx);
    cudaGetSymbolAddress((void**)&imgH, g_img_hi);   cudaGetSymbolAddress((void**)&imgL, g_img_lo);
    cudaGetSymbolAddress((void**)&featH, g_feat_hi); cudaGetSymbolAddress((void**)&featL, g_feat_lo);
    cudaGetSymbolAddress((void**)&etH, g_etok_hi);   cudaGetSymbolAddress((void**)&etL, g_etok_lo);
    cudaGetSymbolAddress((void**)&stH, g_st_hi);     cudaGetSymbolAddress((void**)&stL, g_st_lo);
    cudaGetSymbolAddress((void**)&f1oH, g_f1o_hi);   cudaGetSymbolAddress((void**)&f1oL, g_f1o_lo);
    cudaGetSymbolAddress((void**)&wfcH, g_wfc_h);
    cudaGetSymbolAddress((void**)&w1H,  g_w1_h);
    cudaGetSymbolAddress((void**)&gk2H, g_gk2_h);
    cudaGetSymbolAddress((void**)&f1wH, g_f1w_h);
    cudaGetSymbolAddress((void**)&f2wH, g_f2w_h);

    const int SMEM_SZ = 3 * STAGE;   // 87552 B, 3-stage pipeline
    cudaFuncSetAttribute(mma_gemm_hf, cudaFuncAttributeMaxDynamicSharedMemorySize, SMEM_SZ);
    const int STEP_SMEM = 56704 * 4;   // 226816 B
    cudaFuncSetAttribute(step_loop_kernel, cudaFuncAttributeMaxDynamicSharedMemorySize, STEP_SMEM);

    cvt_fused<<<20804, 256>>>(img, W_fc, W1, gru_k, fc1_w, fc2_w, W2);
    gather_kernel<<<6016, 256>>>(target, emb);
    mma_gemm_hf<<<dim3(2, 64), 256, SMEM_SZ>>>(imgH, imgL, wfcH, b_fc,
                                               features, featH, featL, 8192, 256, 2048, 1, 0);
    mma_gemm_hf<<<dim3(4, 64), 256, SMEM_SZ>>>(featH, featL, w1H, b1,
                                               featw1, nullptr, nullptr, 8192, 512, 256, 0, 0);
    mma_gemm_hf<<<dim3(12, 47), 256, SMEM_SZ>>>(etH, etL, gk2H, gru_b,
                                                embmx, nullptr, nullptr, 6016, 1536, 256, 0, 0);
    step_loop_kernel<<<128, 256, STEP_SMEM>>>(V, bV, b2, gru_b);
    mma_gemm_hf<<<dim3(4, 47), 256, SMEM_SZ>>>(stH, stL, f1wH, fc1_b,
                                               nullptr, f1oH, f1oL, 6016, 512, 512, 0, 0);
    mma_gemm_hf<<<dim3(40, 47), 256, SMEM_SZ>>>(f1oH, f1oL, f2wH, fc2_b,
                                                out, nullptr, nullptr, 6016, 5000, 512, 0, 1);
}

// round 14
// speedup vs baseline: 1.3567x; 1.3567x over previous
#include <cuda_runtime.h>
#include <cuda_fp16.h>
#include <cstdint>

#define TS 47

// ---------------- fp32 scratch ----------------
__device__ __align__(128) float g_featw1 [8192 * 512];
__device__ __align__(128) float g_features[8192 * 256];
__device__ __align__(128) float g_embmx  [6016 * 1536];
__device__ __align__(128) float g_hidw2  [128 * 512];

// ---------------- fp16 planes ----------------
__device__ __align__(128) __half g_img_hi [8192 * 2048], g_img_lo [8192 * 2048];
__device__ __align__(128) __half g_feat_hi[8192 * 256],  g_feat_lo[8192 * 256];
__device__ __align__(128) __half g_etok_hi[6016 * 256],  g_etok_lo[6016 * 256];
__device__ __align__(128) __half g_st_hi  [6016 * 512],  g_st_lo  [6016 * 512];
__device__ __align__(128) __half g_f1o_hi [6016 * 512],  g_f1o_lo [6016 * 512];
__device__ __align__(128) __half g_ctx_hi [128 * 256],   g_ctx_lo [128 * 256];
__device__ __align__(128) __half g_wfc_h [2048 * 256];
__device__ __align__(128) __half g_w1_h  [256 * 512];
__device__ __align__(128) __half g_gk1_h [256 * 1536];
__device__ __align__(128) __half g_gk2_h [256 * 1536];
__device__ __align__(128) __half g_w2_h  [512 * 512];
__device__ __align__(128) __half g_f1w_h [512 * 512];
__device__ __align__(128) __half g_f2w_h [512 * 5000];

// ---------------- barrier state (monotonic, replay-safe) ----------------
__device__ unsigned g_flags[128];
__device__ unsigned g_release;
__device__ unsigned g_epoch;

// ---------------- helpers ----------------
__device__ __forceinline__ float tanh_apx(float x) {
    float y;
    asm("tanh.approx.f32 %0, %1;" : "=f"(y) : "f"(x));
    return y;
}
__device__ __forceinline__ unsigned ld_acq(const unsigned* p) {
    unsigned v;
    asm volatile("ld.acquire.gpu.global.u32 %0, [%1];" : "=r"(v) : "l"(p));
    return v;
}
__device__ __forceinline__ void st_rel(unsigned* p, unsigned v) {
    asm volatile("st.release.gpu.global.u32 [%0], %1;" :: "l"(p), "r"(v) : "memory");
}
// two-hop barrier (R12-proven): block0 aggregates flags, publishes one release word
__device__ __forceinline__ void grid_bar2(int bid, int tid, unsigned tgt) {
    __syncthreads();
    if (bid == 0) {
        if (tid > 0 && tid < 128) {
            while ((int)(ld_acq(&g_flags[tid]) - tgt) < 0) { }
        }
        __syncthreads();
        if (tid == 0) st_rel(&g_release, tgt);
    } else {
        if (tid == 0) {
            st_rel(&g_flags[bid], tgt);
            while ((int)(ld_acq(&g_release) - tgt) < 0) { }
        }
        __syncthreads();
    }
}
__device__ __forceinline__ uint32_t smem_u32(const void* p) {
    uint32_t a;
    asm("{ .reg .u64 t; cvta.to.shared.u64 t, %1; cvt.u32.u64 %0, t; }"
        : "=r"(a) : "l"(p));
    return a;
}
__device__ __forceinline__ void ldsm_x4(uint32_t* r, uint32_t addr) {
    asm volatile("ldmatrix.sync.aligned.m8n8.x4.shared.b16 {%0,%1,%2,%3}, [%4];"
        : "=r"(r[0]), "=r"(r[1]), "=r"(r[2]), "=r"(r[3]) : "r"(addr));
}
__device__ __forceinline__ void ldsm_x2t(uint32_t* r, uint32_t addr) {
    asm volatile("ldmatrix.sync.aligned.m8n8.x2.trans.shared.b16 {%0,%1}, [%2];"
        : "=r"(r[0]), "=r"(r[1]) : "r"(addr));
}
__device__ __forceinline__ void mma_f16(float* c, const uint32_t* a, const uint32_t* b) {
    asm volatile("mma.sync.aligned.m16n8k16.row.col.f32.f16.f16.f32 "
        "{%0,%1,%2,%3},{%4,%5,%6,%7},{%8,%9},{%0,%1,%2,%3};"
        : "+f"(c[0]), "+f"(c[1]), "+f"(c[2]), "+f"(c[3])
        : "r"(a[0]), "r"(a[1]), "r"(a[2]), "r"(a[3]), "r"(b[0]), "r"(b[1]));
}
__device__ __forceinline__ uint32_t packh(__half a, __half b) {
    __half2 t = __halves2half2(a, b);
    return *(uint32_t*)&t;
}
__device__ __forceinline__ void cpasync16(uint32_t sa, const void* ga, int sz) {
    asm volatile("cp.async.cg.shared.global [%0], [%1], 16, %2;"
                 :: "r"(sa), "l"(ga), "r"(sz) : "memory");
}
#define CP_COMMIT() asm volatile("cp.async.commit_group;" ::: "memory")

// ---------------- fused fp32 -> fp16 converts (ONE launch) ----------------
__global__ void cvt_fused(const float* __restrict__ img, const float* __restrict__ W_fc,
                          const float* __restrict__ W1, const float* __restrict__ gru_k,
                          const float* __restrict__ fc1_w, const float* __restrict__ fc2_w,
                          const float* __restrict__ W2)
{
    int blk = blockIdx.x;
    const float* src;
    __half *hi = nullptr, *lo = nullptr, *one = nullptr;
    int base;
    if (blk < 16384)      { src = img;              hi = g_img_hi; lo = g_img_lo; base = blk; }
    else if (blk < 16896) { src = W_fc;             one = g_wfc_h; base = blk - 16384; }
    else if (blk < 17024) { src = W1;               one = g_w1_h;  base = blk - 16896; }
    else if (blk < 17408) { src = gru_k + 256*1536; one = g_gk2_h; base = blk - 17024; }
    else if (blk < 17664) { src = fc1_w;            one = g_f1w_h; base = blk - 17408; }
    else if (blk < 20164) { src = fc2_w;            one = g_f2w_h; base = blk - 17664; }
    else if (blk < 20420) { src = W2;               one = g_w2_h;  base = blk - 20164; }
    else                  { src = gru_k;            one = g_gk1_h; base = blk - 20420; }
    int i = (base * 256 + threadIdx.x) * 4;
    float4 v = *(const float4*)(src + i);
    __half hx = __float2half(v.x), hy = __float2half(v.y);
    __half hz = __float2half(v.z), hw = __float2half(v.w);
    if (one) {
        *(uint2*)(one + i) = make_uint2(packh(hx, hy), packh(hz, hw));
    } else {
        *(uint2*)(hi + i) = make_uint2(packh(hx, hy), packh(hz, hw));
        __half lx = __float2half(v.x - __half2float(hx));
        __half ly = __float2half(v.y - __half2float(hy));
        __half lz = __float2half(v.z - __half2float(hz));
        __half lw = __float2half(v.w - __half2float(hw));
        *(uint2*)(lo + i) = make_uint2(packh(lx, ly), packh(lz, lw));
    }
}

// ---------------- fp16 2-term tensor-core GEMM, 3-stage cp.async pipeline ----------------
#define OFF_ALO 10240
#define OFF_B   20480
#define STAGE   29184

__global__ void __launch_bounds__(256, 2) mma_gemm_hf(
    const __half* __restrict__ Ahi, const __half* __restrict__ Alo,
    const __half* __restrict__ B,
    const float* __restrict__ bias, float* __restrict__ C,
    __half* __restrict__ Chi, __half* __restrict__ Clo,
    int M, int N, int K, int relu, int remap)
{
    extern __shared__ char smem[];
    const int tid = threadIdx.x;
    const int wid = tid >> 5, lane = tid & 31;
    const int bm = blockIdx.y * 128, bn = blockIdx.x * 128;
    const int wm = (wid >> 2) * 64;
    const int wn = (wid & 3) * 32;
    const uint32_t sbase = smem_u32(smem);

    float acc[4][4][4] = {};
    const int nc = K >> 5;

    auto issue = [&](int c) {
        int k0 = c << 5;
        uint32_t sb = sbase + (c % 3) * STAGE;
        #pragma unroll
        for (int i = 0; i < 2; i++) {
            int task = tid + (i << 8);
            int m = task >> 2, k8 = (task & 3) << 3;
            uint32_t sa = sb + m * 80 + (k8 << 1);
            size_t go = (size_t)(bm + m) * K + k0 + k8;
            cpasync16(sa, Ahi + go, 16);
            cpasync16(sa + OFF_ALO, Alo + go, 16);
        }
        #pragma unroll
        for (int i = 0; i < 2; i++) {
            int task = tid + (i << 8);
            int kk = task >> 4, n8 = (task & 15) << 3;
            int gc = bn + n8;
            uint32_t sa = sb + OFF_B + kk * 272 + (n8 << 1);
            size_t go = (size_t)(k0 + kk) * N + gc;
            int sz = (gc + 8 <= N) ? 16 : 0;
            cpasync16(sa, B + go, sz);
        }
        CP_COMMIT();
    };

    issue(0);
    if (nc > 1) issue(1);

    for (int c = 0; c < nc; c++) {
        if (c + 2 < nc) {
            issue(c + 2);
            asm volatile("cp.async.wait_group 2;" ::: "memory");
        } else if (c + 1 < nc) {
            asm volatile("cp.async.wait_group 1;" ::: "memory");
        } else {
            asm volatile("cp.async.wait_group 0;" ::: "memory");
        }
        __syncthreads();

        uint32_t base = sbase + (c % 3) * STAGE;
        uint32_t aAhi = base, aAlo = base + OFF_ALO;
        uint32_t aB = base + OFF_B;

        #pragma unroll
        for (int kk = 0; kk < 2; kk++) {
            int kb = kk * 16;
            uint32_t ahi[4][4], alo[4][4];
            #pragma unroll
            for (int im = 0; im < 4; im++) {
                int row = wm + im * 16 + (lane & 15);
                uint32_t off = row * 80 + kb * 2 + ((lane >> 4) << 4);
                ldsm_x4(ahi[im], aAhi + off);
                ldsm_x4(alo[im], aAlo + off);
            }
            #pragma unroll
            for (int jn = 0; jn < 4; jn++) {
                int n = wn + jn * 8;
                uint32_t off = (kb + (lane & 15)) * 272 + n * 2;
                uint32_t bb[2];
                ldsm_x2t(bb, aB + off);
                #pragma unroll
                for (int im = 0; im < 4; im++) {
                    mma_f16(acc[im][jn], ahi[im], bb);
                    mma_f16(acc[im][jn], alo[im], bb);
                }
            }
        }
        __syncthreads();
    }

    int tr = lane >> 2, tc = (lane & 3) << 1;
    #pragma unroll
    for (int im = 0; im < 4; im++) {
        #pragma unroll
        for (int half = 0; half < 2; half++) {
            int grow = bm + wm + im * 16 + tr + half * 8;
            size_t ro;
            if (remap) {
                int t = grow >> 7, b = grow & 127;
                ro = ((size_t)b * TS + t) * (size_t)N;
            } else {
                ro = (size_t)grow * (size_t)N;
            }
            #pragma unroll
            for (int jn = 0; jn < 4; jn++) {
                int gc = bn + wn + jn * 8 + tc;
                if (gc < N) {
                    float v0 = acc[im][jn][half * 2 + 0] + bias[gc];
                    float v1 = acc[im][jn][half * 2 + 1] + bias[gc + 1];
                    if (relu) { v0 = fmaxf(v0, 0.f); v1 = fmaxf(v1, 0.f); }
                    if (C) *(float2*)(C + ro + gc) = make_float2(v0, v1);
                    if (Chi) {
                        __half h0 = __float2half(v0);
                        __half h1 = __float2half(v1);
                        *(uint32_t*)(Chi + ro + gc) = packh(h0, h1);
                        __half l0 = __float2half(v0 - __half2float(h0));
                        __half l1 = __float2half(v1 - __half2float(h1));
                        *(uint32_t*)(Clo + ro + gc) = packh(l0, l1);
                    }
                }
            }
        }
    }
}

// ---------------- token embedding gather -> fp16 pair ----------------
__global__ void gather_kernel(const int* __restrict__ target,
                              const float* __restrict__ emb)
{
    int row = blockIdx.x;
    int e = threadIdx.x;
    int t = row >> 7, b = row & 127;
    int tok = (t == 0) ? 1 : target[b * 48 + t];
    float v = emb[(size_t)tok * 256 + e];
    __half h = __float2half(v);
    g_etok_hi[(size_t)row * 256 + e] = h;
    g_etok_lo[(size_t)row * 256 + e] = __float2half(v - __half2float(h));
}

// ---------------- persistent step loop (R12 structure, two-hop barrier) ----------------
__global__ __launch_bounds__(256) void step_loop_kernel(
    const float* __restrict__ V, const float* __restrict__ bV,
    const float* __restrict__ b2, const float* __restrict__ gru_b)
{
    extern __shared__ float dsm[];
    float* sFW1  = dsm;
    float* sFEAT = dsm + 32768;
    float* work  = dsm + 49152;

    const int bid = blockIdx.x;
    const int tid = threadIdx.x;
    const int wid = tid >> 5, lane = tid & 31;
    unsigned bar = g_epoch;
    const unsigned bar0 = bar;

    for (int j = tid; j < 8192; j += 256)
        *(float4*)&sFW1[j * 4] = *(const float4*)(g_featw1 + (size_t)bid * 32768 + j * 4);
    for (int j = tid; j < 4096; j += 256)
        *(float4*)&sFEAT[j * 4] = *(const float4*)(g_features + (size_t)bid * 16384 + j * 4);
    __syncthreads();

    const uint32_t wb = smem_u32(work);

    for (int t = 0; t < TS; t++) {
        // ---- Phase A: hidw2 = states[t-1] @ W2, fp16 2-term mma (64 blocks) ----
        if (t > 0) {
            if (bid < 64) {
                int bm = (bid >> 4) * 32, bn = (bid & 15) * 32;
                const __half* Ah = g_st_hi + (size_t)(t - 1) * 65536;
                const __half* Al = g_st_lo + (size_t)(t - 1) * 65536;

                auto issueA = [&](int c) {
                    uint32_t st = wb + (c & 1) * 14336;
                    int k0 = c * 64;
                    #pragma unroll
                    for (int i = 0; i < 2; i++) {
                        int idx = tid + (i << 8);
                        int r = idx >> 4, rem = idx & 15, pl = rem >> 3, seg = rem & 7;
                        const __half* src = (pl ? Al : Ah) + (size_t)(bm + r) * 512 + k0 + seg * 8;
                        cpasync16(st + pl * 4608 + r * 144 + seg * 16, src, 16);
                    }
                    {
                        int kr = tid >> 2, seg = tid & 3;
                        cpasync16(st + 9216 + kr * 80 + seg * 16,
                                  g_w2_h + (size_t)(k0 + kr) * 512 + bn + seg * 8, 16);
                    }
                    CP_COMMIT();
                };
                issueA(0); issueA(1);

                int wmi = (wid >> 2) * 16;
                int wni = (wid & 3) * 8;
                float acc[4] = {};
                for (int c = 0; c < 8; c++) {
                    if (c < 7) asm volatile("cp.async.wait_group 1;" ::: "memory");
                    else       asm volatile("cp.async.wait_group 0;" ::: "memory");
                    __syncthreads();
                    uint32_t st = wb + (c & 1) * 14336;
                    #pragma unroll
                    for (int ks = 0; ks < 4; ks++) {
                        uint32_t ahi[4], alo[4], bb[2];
                        int row = wmi + (lane & 15);
                        uint32_t aoff = row * 144 + ks * 32 + ((lane >> 4) << 4);
                        ldsm_x4(ahi, st + aoff);
                        ldsm_x4(alo, st + 4608 + aoff);
                        uint32_t boff = 9216 + (ks * 16 + (lane & 15)) * 80 + wni * 2;
                        ldsm_x2t(bb, st + boff);
                        mma_f16(acc, ahi, bb);
                        mma_f16(acc, alo, bb);
                    }
                    __syncthreads();
                    if (c + 2 < 8) issueA(c + 2);
                }
                int tr = lane >> 2, tc2 = (lane & 3) * 2;
                int col = bn + wni + tc2;
                *(float2*)&g_hidw2[(bm + wmi + tr) * 512 + col] = make_float2(acc[0], acc[1]);
                *(float2*)&g_hidw2[(bm + wmi + tr + 8) * 512 + col] = make_float2(acc[2], acc[3]);
            }
            grid_bar2(bid, tid, ++bar);
        }

        // ---- Phase B: Bahdanau attention; emits ctx fp16 pairs ----
        {
            float* hw2 = work;
            float* sV  = work + 512;
            float* sl  = work + 1024;
            int b = bid;
            if (t > 0) {
                hw2[tid]       = g_hidw2[b * 512 + tid]       + b2[tid];
                hw2[tid + 256] = g_hidw2[b * 512 + tid + 256] + b2[tid + 256];
            } else {
                hw2[tid]       = b2[tid];
                hw2[tid + 256] = b2[tid + 256];
            }
            sV[tid]       = V[tid];
            sV[tid + 256] = V[tid + 256];
            __syncthreads();

            #pragma unroll
            for (int p = 0; p < 8; p++) {
                int l = wid * 8 + p;
                const float* row = sFW1 + l * 512;
                float a = 0.f;
                #pragma unroll
                for (int j = 0; j < 16; j++) {
                    int u = lane + j * 32;
                    float s = tanh_apx(row[u] + hw2[u]);
                    a = fmaf(s, sV[u], a);
                }
                #pragma unroll
                for (int o = 16; o; o >>= 1) a += __shfl_xor_sync(0xffffffffu, a, o);
                if (lane == 0) sl[l] = a + bV[0];
            }
            __syncthreads();

            if (tid < 32) {
                float v0 = sl[tid], v1 = sl[tid + 32];
                float m = fmaxf(v0, v1);
                #pragma unroll
                for (int o = 16; o; o >>= 1) m = fmaxf(m, __shfl_xor_sync(0xffffffffu, m, o));
                float e0 = __expf(v0 - m), e1 = __expf(v1 - m);
                float s = e0 + e1;
                #pragma unroll
                for (int o = 16; o; o >>= 1) s += __shfl_xor_sync(0xffffffffu, s, o);
                float inv = 1.0f / s;
                sl[tid] = e0 * inv;
                sl[tid + 32] = e1 * inv;
            }
            __syncthreads();

            float c = 0.f;
            #pragma unroll 8
            for (int l = 0; l < 64; l++)
                c = fmaf(sl[l], sFEAT[l * 256 + tid], c);
            __half h = __float2half(c);
            g_ctx_hi[b * 256 + tid] = h;
            g_ctx_lo[b * 256 + tid] = __float2half(c - __half2float(h));
        }
        grid_bar2(bid, tid, ++bar);

        // ---- Phase C+D: mx = ctx @ gru_k[:256] (fp16 mma) + GRU pointwise ----
        {
            int b0 = (bid >> 4) * 16;
            int u0 = (bid & 15) * 32;
            const uint32_t CTXLO = 8448, WST = 16896, WSZ = 6656;

            auto issueW = [&](int c) {
                uint32_t st = wb + WST + (c & 1) * WSZ;
                int k0 = c * 32;
                #pragma unroll
                for (int i = 0; i < 2; i++) {
                    int idx = tid + (i << 8);
                    if (idx < 384) {
                        int g = idx >> 7, rem = idx & 127, kr = rem >> 2, seg = rem & 3;
                        cpasync16(st + kr * 208 + g * 64 + seg * 16,
                                  g_gk1_h + (size_t)(k0 + kr) * 1536 + g * 512 + u0 + seg * 8, 16);
                    }
                }
            };
            {
                #pragma unroll
                for (int i = 0; i < 4; i++) {
                    int idx = tid + (i << 8);
                    int r = idx >> 6, rem = idx & 63, pl = rem >> 5, seg = rem & 31;
                    const __half* src = (pl ? g_ctx_lo : g_ctx_hi) + (size_t)(b0 + r) * 256 + seg * 8;
                    cpasync16(wb + pl * CTXLO + r * 528 + seg * 16, src, 16);
                }
                issueW(0); CP_COMMIT();
                issueW(1); CP_COMMIT();
            }

            float acc0[4] = {}, acc1[4] = {};
            int tile0 = wid, tile1 = wid + 8;

            for (int c = 0; c < 8; c++) {
                if (c < 7) asm volatile("cp.async.wait_group 1;" ::: "memory");
                else       asm volatile("cp.async.wait_group 0;" ::: "memory");
                __syncthreads();
                uint32_t st = wb + WST + (c & 1) * WSZ;
                #pragma unroll
                for (int ks = 0; ks < 2; ks++) {
                    uint32_t ahi[4], alo[4], bb[2];
                    int row = lane & 15;
                    uint32_t aoff = row * 528 + (c * 32 + ks * 16) * 2 + ((lane >> 4) << 4);
                    ldsm_x4(ahi, wb + aoff);
                    ldsm_x4(alo, wb + CTXLO + aoff);
                    {
                        int g = tile0 >> 2, ns = tile0 & 3;
                        ldsm_x2t(bb, st + (ks * 16 + (lane & 15)) * 208 + g * 64 + ns * 16);
                        mma_f16(acc0, ahi, bb);
                        mma_f16(acc0, alo, bb);
                    }
                    if (wid < 4) {
                        int g = tile1 >> 2, ns = tile1 & 3;
                        ldsm_x2t(bb, st + (ks * 16 + (lane & 15)) * 208 + g * 64 + ns * 16);
                        mma_f16(acc1, ahi, bb);
                        mma_f16(acc1, alo, bb);
                    }
                }
                __syncthreads();
                if (c + 2 < 8) { issueW(c + 2); CP_COMMIT(); }
            }

            __syncthreads();
            float* mxs = work;
            int tr = lane >> 2, tc2 = (lane & 3) * 2;
            {
                int cb = (tile0 >> 2) * 32 + (tile0 & 3) * 8 + tc2;
                mxs[tr * 104 + cb] = acc0[0];       mxs[tr * 104 + cb + 1] = acc0[1];
                mxs[(tr + 8) * 104 + cb] = acc0[2]; mxs[(tr + 8) * 104 + cb + 1] = acc0[3];
            }
            if (wid < 4) {
                int cb = (tile1 >> 2) * 32 + (tile1 & 3) * 8 + tc2;
                mxs[tr * 104 + cb] = acc1[0];       mxs[tr * 104 + cb + 1] = acc1[1];
                mxs[(tr + 8) * 104 + cb] = acc1[2]; mxs[(tr + 8) * 104 + cb + 1] = acc1[3];
            }
            __syncthreads();

            #pragma unroll
            for (int i = 0; i < 2; i++) {
                int it = tid + (i << 8);
                int ul = it & 31, b = it >> 5;
                int u = u0 + ul;
                size_t r = (size_t)t * 128 + (b0 + b);
                float xz = mxs[b * 104 + ul]      + g_embmx[r * 1536 + u];
                float xr = mxs[b * 104 + 32 + ul] + g_embmx[r * 1536 + 512 + u];
                float xh = mxs[b * 104 + 64 + ul] + g_embmx[r * 1536 + 1024 + u];
                float rz = gru_b[1536 + u];
                float rr = gru_b[2048 + u];
                float rh = gru_b[2560 + u];
                float z  = 1.f / (1.f + __expf(-(xz + rz)));
                float rg = 1.f / (1.f + __expf(-(xr + rr)));
                float hh = tanh_apx(xh + rg * rh);
                float st = (1.f - z) * hh;
                __half h = __float2half(st);
                g_st_hi[r * 512 + u] = h;
                g_st_lo[r * 512 + u] = __float2half(st - __half2float(h));
            }
        }
        grid_bar2(bid, tid, ++bar);
    }

    if (bid == 0 && tid == 0) g_epoch = bar0 + (unsigned)(3 * TS - 1);
}

// ---------------- launch ----------------
extern "C" void kernel_launch(void* const* d_in, const int* in_sizes, int n_in,
                              void* d_out, int out_size)
{
    const float* img    = (const float*)d_in[0];
    const int*   target = (const int*)  d_in[1];
    const float* W_fc   = (const float*)d_in[2];
    const float* b_fc   = (const float*)d_in[3];
    const float* W1     = (const float*)d_in[4];
    const float* b1     = (const float*)d_in[5];
    const float* W2     = (const float*)d_in[6];
    const float* b2     = (const float*)d_in[7];
    const float* V      = (const float*)d_in[8];
    const float* bV     = (const float*)d_in[9];
    const float* emb    = (const float*)d_in[10];
    const float* gru_k  = (const float*)d_in[11];
    /* d_in[12] = gru_rk : dead (zero GRU state) */
    const float* gru_b  = (const float*)d_in[13];
    const float* fc1_w  = (const float*)d_in[14];
    const float* fc1_b  = (const float*)d_in[15];
    const float* fc2_w  = (const float*)d_in[16];
    const float* fc2_b  = (const float*)d_in[17];
    float* out = (float*)d_out;

    float *featw1, *features, *embmx;
    __half *imgH, *imgL, *featH, *featL, *etH, *etL, *stH, *stL, *f1oH, *f1oL;
    __half *wfcH, *w1H, *gk2H, *f1wH, *f2wH;
    cudaGetSymbolAddress((void**)&featw1,   g_featw1);
    cudaGetSymbolAddress((void**)&features, g_features);
    cudaGetSymbolAddress((void**)&embmx,    g_embmx);
    cudaGetSymbolAddress((void**)&imgH, g_img_hi);   cudaGetSymbolAddress((void**)&imgL, g_img_lo);
    cudaGetSymbolAddress((void**)&featH, g_feat_hi); cudaGetSymbolAddress((void**)&featL, g_feat_lo);
    cudaGetSymbolAddress((void**)&etH, g_etok_hi);   cudaGetSymbolAddress((void**)&etL, g_etok_lo);
    cudaGetSymbolAddress((void**)&stH, g_st_hi);     cudaGetSymbolAddress((void**)&stL, g_st_lo);
    cudaGetSymbolAddress((void**)&f1oH, g_f1o_hi);   cudaGetSymbolAddress((void**)&f1oL, g_f1o_lo);
    cudaGetSymbolAddress((void**)&wfcH, g_wfc_h);
    cudaGetSymbolAddress((void**)&w1H,  g_w1_h);
    cudaGetSymbolAddress((void**)&gk2H, g_gk2_h);
    cudaGetSymbolAddress((void**)&f1wH, g_f1w_h);
    cudaGetSymbolAddress((void**)&f2wH, g_f2w_h);

    const int SMEM_SZ = 3 * STAGE;   // 87552 B, 3-stage pipeline
    cudaFuncSetAttribute(mma_gemm_hf, cudaFuncAttributeMaxDynamicSharedMemorySize, SMEM_SZ);
    const int STEP_SMEM = 56704 * 4;   // 226816 B
    cudaFuncSetAttribute(step_loop_kernel, cudaFuncAttributeMaxDynamicSharedMemorySize, STEP_SMEM);

    cvt_fused<<<20804, 256>>>(img, W_fc, W1, gru_k, fc1_w, fc2_w, W2);
    gather_kernel<<<6016, 256>>>(target, emb);
    mma_gemm_hf<<<dim3(2, 64), 256, SMEM_SZ>>>(imgH, imgL, wfcH, b_fc,
                                               features, featH, featL, 8192, 256, 2048, 1, 0);
    mma_gemm_hf<<<dim3(4, 64), 256, SMEM_SZ>>>(featH, featL, w1H, b1,
                                               featw1, nullptr, nullptr, 8192, 512, 256, 0, 0);
    mma_gemm_hf<<<dim3(12, 47), 256, SMEM_SZ>>>(etH, etL, gk2H, gru_b,
                                                embmx, nullptr, nullptr, 6016, 1536, 256, 0, 0);
    step_loop_kernel<<<128, 256, STEP_SMEM>>>(V, bV, b2, gru_b);
    mma_gemm_hf<<<dim3(4, 47), 256, SMEM_SZ>>>(stH, stL, f1wH, fc1_b,
                                               nullptr, f1oH, f1oL, 6016, 512, 512, 0, 0);
    mma_gemm_hf<<<dim3(40, 47), 256, SMEM_SZ>>>(f1oH, f1oL, f2wH, fc2_b,
                                                out, nullptr, nullptr, 6016, 5000, 512, 0, 1);
}

// round 15
// speedup vs baseline: 1.6051x; 1.1831x over previous
#include <cuda_runtime.h>
#include <cuda_fp16.h>
#include <cstdint>

#define TS 47

// ---------------- fp32 scratch ----------------
__device__ __align__(128) float g_featw1 [8192 * 512];
__device__ __align__(128) float g_features[8192 * 256];
__device__ __align__(128) float g_embmx  [6016 * 1536];
__device__ __align__(128) float g_hidw2p [16 * 128 * 512];   // per-u-slice partials

// ---------------- fp16 planes ----------------
__device__ __align__(128) __half g_img_hi [8192 * 2048], g_img_lo [8192 * 2048];
__device__ __align__(128) __half g_feat_hi[8192 * 256],  g_feat_lo[8192 * 256];
__device__ __align__(128) __half g_etok_hi[6016 * 256],  g_etok_lo[6016 * 256];
__device__ __align__(128) __half g_st_hi  [6016 * 512],  g_st_lo  [6016 * 512];
__device__ __align__(128) __half g_f1o_hi [6016 * 512],  g_f1o_lo [6016 * 512];
__device__ __align__(128) __half g_ctx_hi [128 * 256],   g_ctx_lo [128 * 256];
__device__ __align__(128) __half g_wfc_h [2048 * 256];
__device__ __align__(128) __half g_w1_h  [256 * 512];
__device__ __align__(128) __half g_gk1_h [256 * 1536];
__device__ __align__(128) __half g_gk2_h [256 * 1536];
__device__ __align__(128) __half g_w2_h  [512 * 512];
__device__ __align__(128) __half g_f1w_h [512 * 512];
__device__ __align__(128) __half g_f2w_h [512 * 5000];

// ---------------- barrier state (monotonic, replay-safe) ----------------
__device__ unsigned g_flags[128];
__device__ unsigned g_release;
__device__ unsigned g_epoch;

// ---------------- helpers ----------------
__device__ __forceinline__ float tanh_apx(float x) {
    float y;
    asm("tanh.approx.f32 %0, %1;" : "=f"(y) : "f"(x));
    return y;
}
__device__ __forceinline__ unsigned ld_acq(const unsigned* p) {
    unsigned v;
    asm volatile("ld.acquire.gpu.global.u32 %0, [%1];" : "=r"(v) : "l"(p));
    return v;
}
__device__ __forceinline__ void st_rel(unsigned* p, unsigned v) {
    asm volatile("st.release.gpu.global.u32 [%0], %1;" :: "l"(p), "r"(v) : "memory");
}
// two-hop barrier (R12-proven)
__device__ __forceinline__ void grid_bar2(int bid, int tid, unsigned tgt) {
    __syncthreads();
    if (bid == 0) {
        if (tid > 0 && tid < 128) {
            while ((int)(ld_acq(&g_flags[tid]) - tgt) < 0) { }
        }
        __syncthreads();
        if (tid == 0) st_rel(&g_release, tgt);
    } else {
        if (tid == 0) {
            st_rel(&g_flags[bid], tgt);
            while ((int)(ld_acq(&g_release) - tgt) < 0) { }
        }
        __syncthreads();
    }
}
__device__ __forceinline__ uint32_t smem_u32(const void* p) {
    uint32_t a;
    asm("{ .reg .u64 t; cvta.to.shared.u64 t, %1; cvt.u32.u64 %0, t; }"
        : "=r"(a) : "l"(p));
    return a;
}
__device__ __forceinline__ void ldsm_x4(uint32_t* r, uint32_t addr) {
    asm volatile("ldmatrix.sync.aligned.m8n8.x4.shared.b16 {%0,%1,%2,%3}, [%4];"
        : "=r"(r[0]), "=r"(r[1]), "=r"(r[2]), "=r"(r[3]) : "r"(addr));
}
__device__ __forceinline__ void ldsm_x2t(uint32_t* r, uint32_t addr) {
    asm volatile("ldmatrix.sync.aligned.m8n8.x2.trans.shared.b16 {%0,%1}, [%2];"
        : "=r"(r[0]), "=r"(r[1]) : "r"(addr));
}
__device__ __forceinline__ void mma_f16(float* c, const uint32_t* a, const uint32_t* b) {
    asm volatile("mma.sync.aligned.m16n8k16.row.col.f32.f16.f16.f32 "
        "{%0,%1,%2,%3},{%4,%5,%6,%7},{%8,%9},{%0,%1,%2,%3};"
        : "+f"(c[0]), "+f"(c[1]), "+f"(c[2]), "+f"(c[3])
        : "r"(a[0]), "r"(a[1]), "r"(a[2]), "r"(a[3]), "r"(b[0]), "r"(b[1]));
}
__device__ __forceinline__ uint32_t packh(__half a, __half b) {
    __half2 t = __halves2half2(a, b);
    return *(uint32_t*)&t;
}
__device__ __forceinline__ void cpasync16(uint32_t sa, const void* ga, int sz) {
    asm volatile("cp.async.cg.shared.global [%0], [%1], 16, %2;"
                 :: "r"(sa), "l"(ga), "r"(sz) : "memory");
}
#define CP_COMMIT() asm volatile("cp.async.commit_group;" ::: "memory")

// ---------------- fused fp32 -> fp16 converts (ONE launch) ----------------
__global__ void cvt_fused(const float* __restrict__ img, const float* __restrict__ W_fc,
                          const float* __restrict__ W1, const float* __restrict__ gru_k,
                          const float* __restrict__ fc1_w, const float* __restrict__ fc2_w,
                          const float* __restrict__ W2)
{
    int blk = blockIdx.x;
    const float* src;
    __half *hi = nullptr, *lo = nullptr, *one = nullptr;
    int base;
    if (blk < 16384)      { src = img;              hi = g_img_hi; lo = g_img_lo; base = blk; }
    else if (blk < 16896) { src = W_fc;             one = g_wfc_h; base = blk - 16384; }
    else if (blk < 17024) { src = W1;               one = g_w1_h;  base = blk - 16896; }
    else if (blk < 17408) { src = gru_k + 256*1536; one = g_gk2_h; base = blk - 17024; }
    else if (blk < 17664) { src = fc1_w;            one = g_f1w_h; base = blk - 17408; }
    else if (blk < 20164) { src = fc2_w;            one = g_f2w_h; base = blk - 17664; }
    else if (blk < 20420) { src = W2;               one = g_w2_h;  base = blk - 20164; }
    else                  { src = gru_k;            one = g_gk1_h; base = blk - 20420; }
    int i = (base * 256 + threadIdx.x) * 4;
    float4 v = *(const float4*)(src + i);
    __half hx = __float2half(v.x), hy = __float2half(v.y);
    __half hz = __float2half(v.z), hw = __float2half(v.w);
    if (one) {
        *(uint2*)(one + i) = make_uint2(packh(hx, hy), packh(hz, hw));
    } else {
        *(uint2*)(hi + i) = make_uint2(packh(hx, hy), packh(hz, hw));
        __half lx = __float2half(v.x - __half2float(hx));
        __half ly = __float2half(v.y - __half2float(hy));
        __half lz = __float2half(v.z - __half2float(hz));
        __half lw = __float2half(v.w - __half2float(hw));
        *(uint2*)(lo + i) = make_uint2(packh(lx, ly), packh(lz, lw));
    }
}

// ---------------- fp16 2-term tensor-core GEMM, 2-stage cp.async (R12-proven) ----------------
#define OFF_ALO 10240
#define OFF_B   20480
#define STAGE   29184

__global__ void __launch_bounds__(256, 2) mma_gemm_hf(
    const __half* __restrict__ Ahi, const __half* __restrict__ Alo,
    const __half* __restrict__ B,
    const float* __restrict__ bias, float* __restrict__ C,
    __half* __restrict__ Chi, __half* __restrict__ Clo,
    int M, int N, int K, int relu, int remap)
{
    extern __shared__ char smem[];
    const int tid = threadIdx.x;
    const int wid = tid >> 5, lane = tid & 31;
    const int bm = blockIdx.y * 128, bn = blockIdx.x * 128;
    const int wm = (wid >> 2) * 64;
    const int wn = (wid & 3) * 32;
    const uint32_t sbase = smem_u32(smem);

    float acc[4][4][4] = {};
    const int nc = K >> 5;

    auto issue = [&](int k0, int s) {
        uint32_t sb = sbase + s * STAGE;
        #pragma unroll
        for (int i = 0; i < 2; i++) {
            int task = tid + (i << 8);
            int m = task >> 2, k8 = (task & 3) << 3;
            uint32_t sa = sb + m * 80 + (k8 << 1);
            size_t go = (size_t)(bm + m) * K + k0 + k8;
            cpasync16(sa, Ahi + go, 16);
            cpasync16(sa + OFF_ALO, Alo + go, 16);
        }
        #pragma unroll
        for (int i = 0; i < 2; i++) {
            int task = tid + (i << 8);
            int kk = task >> 4, n8 = (task & 15) << 3;
            int gc = bn + n8;
            uint32_t sa = sb + OFF_B + kk * 272 + (n8 << 1);
            size_t go = (size_t)(k0 + kk) * N + gc;
            int sz = (gc + 8 <= N) ? 16 : 0;
            cpasync16(sa, B + go, sz);
        }
        CP_COMMIT();
    };

    issue(0, 0);

    for (int c = 0; c < nc; c++) {
        int cur = c & 1;
        if (c + 1 < nc) {
            issue((c + 1) << 5, cur ^ 1);
            asm volatile("cp.async.wait_group 1;" ::: "memory");
        } else {
            asm volatile("cp.async.wait_group 0;" ::: "memory");
        }
        __syncthreads();

        uint32_t base = sbase + cur * STAGE;
        uint32_t aAhi = base, aAlo = base + OFF_ALO;
        uint32_t aB = base + OFF_B;

        #pragma unroll
        for (int kk = 0; kk < 2; kk++) {
            int kb = kk * 16;
            uint32_t ahi[4][4], alo[4][4];
            #pragma unroll
            for (int im = 0; im < 4; im++) {
                int row = wm + im * 16 + (lane & 15);
                uint32_t off = row * 80 + kb * 2 + ((lane >> 4) << 4);
                ldsm_x4(ahi[im], aAhi + off);
                ldsm_x4(alo[im], aAlo + off);
            }
            #pragma unroll
            for (int jn = 0; jn < 4; jn++) {
                int n = wn + jn * 8;
                uint32_t off = (kb + (lane & 15)) * 272 + n * 2;
                uint32_t bb[2];
                ldsm_x2t(bb, aB + off);
                #pragma unroll
                for (int im = 0; im < 4; im++) {
                    mma_f16(acc[im][jn], ahi[im], bb);
                    mma_f16(acc[im][jn], alo[im], bb);
                }
            }
        }
        __syncthreads();
    }

    int tr = lane >> 2, tc = (lane & 3) << 1;
    #pragma unroll
    for (int im = 0; im < 4; im++) {
        #pragma unroll
        for (int half = 0; half < 2; half++) {
            int grow = bm + wm + im * 16 + tr + half * 8;
            size_t ro;
            if (remap) {
                int t = grow >> 7, b = grow & 127;
                ro = ((size_t)b * TS + t) * (size_t)N;
            } else {
                ro = (size_t)grow * (size_t)N;
            }
            #pragma unroll
            for (int jn = 0; jn < 4; jn++) {
                int gc = bn + wn + jn * 8 + tc;
                if (gc < N) {
                    float v0 = acc[im][jn][half * 2 + 0] + bias[gc];
                    float v1 = acc[im][jn][half * 2 + 1] + bias[gc + 1];
                    if (relu) { v0 = fmaxf(v0, 0.f); v1 = fmaxf(v1, 0.f); }
                    if (C) *(float2*)(C + ro + gc) = make_float2(v0, v1);
                    if (Chi) {
                        __half h0 = __float2half(v0);
                        __half h1 = __float2half(v1);
                        *(uint32_t*)(Chi + ro + gc) = packh(h0, h1);
                        __half l0 = __float2half(v0 - __half2float(h0));
                        __half l1 = __float2half(v1 - __half2float(h1));
                        *(uint32_t*)(Clo + ro + gc) = packh(l0, l1);
                    }
                }
            }
        }
    }
}

// ---------------- token embedding gather -> fp16 pair ----------------
__global__ void gather_kernel(const int* __restrict__ target,
                              const float* __restrict__ emb)
{
    int row = blockIdx.x;
    int e = threadIdx.x;
    int t = row >> 7, b = row & 127;
    int tok = (t == 0) ? 1 : target[b * 48 + t];
    float v = emb[(size_t)tok * 256 + e];
    __half h = __float2half(v);
    g_etok_hi[(size_t)row * 256 + e] = h;
    g_etok_lo[(size_t)row * 256 + e] = __float2half(v - __half2float(h));
}

// ---------------- persistent step loop: 2 barriers/step, A fused into C ----------------
// dyn smem (floats): sFW1 [0..32767], sFEAT [32768..49151], work [49152..56703]
__global__ __launch_bounds__(256) void step_loop_kernel(
    const float* __restrict__ V, const float* __restrict__ bV,
    const float* __restrict__ b2, const float* __restrict__ gru_b)
{
    extern __shared__ float dsm[];
    float* sFW1  = dsm;
    float* sFEAT = dsm + 32768;
    float* work  = dsm + 49152;

    const int bid = blockIdx.x;
    const int tid = threadIdx.x;
    const int wid = tid >> 5, lane = tid & 31;
    unsigned bar = g_epoch;
    const unsigned bar0 = bar;

    for (int j = tid; j < 8192; j += 256)
        *(float4*)&sFW1[j * 4] = *(const float4*)(g_featw1 + (size_t)bid * 32768 + j * 4);
    for (int j = tid; j < 4096; j += 256)
        *(float4*)&sFEAT[j * 4] = *(const float4*)(g_features + (size_t)bid * 16384 + j * 4);
    __syncthreads();

    const uint32_t wb = smem_u32(work);

    for (int t = 0; t < TS; t++) {
        // ---- Phase B: Bahdanau attention (sums hidw2 partials); emits ctx fp16 pairs ----
        {
            float* hw2 = work;
            float* sV  = work + 512;
            float* sl  = work + 1024;
            int b = bid;
            if (t > 0) {
                #pragma unroll
                for (int i = 0; i < 2; i++) {
                    int idx = tid + (i << 8);
                    float s = b2[idx];
                    #pragma unroll
                    for (int k = 0; k < 16; k++)
                        s += g_hidw2p[(size_t)k * 65536 + b * 512 + idx];
                    hw2[idx] = s;
                }
            } else {
                hw2[tid]       = b2[tid];
                hw2[tid + 256] = b2[tid + 256];
            }
            sV[tid]       = V[tid];
            sV[tid + 256] = V[tid + 256];
            __syncthreads();

            #pragma unroll
            for (int p = 0; p < 8; p++) {
                int l = wid * 8 + p;
                const float* row = sFW1 + l * 512;
                float a = 0.f;
                #pragma unroll
                for (int j = 0; j < 16; j++) {
                    int u = lane + j * 32;
                    float s = tanh_apx(row[u] + hw2[u]);
                    a = fmaf(s, sV[u], a);
                }
                #pragma unroll
                for (int o = 16; o; o >>= 1) a += __shfl_xor_sync(0xffffffffu, a, o);
                if (lane == 0) sl[l] = a + bV[0];
            }
            __syncthreads();

            if (tid < 32) {
                float v0 = sl[tid], v1 = sl[tid + 32];
                float m = fmaxf(v0, v1);
                #pragma unroll
                for (int o = 16; o; o >>= 1) m = fmaxf(m, __shfl_xor_sync(0xffffffffu, m, o));
                float e0 = __expf(v0 - m), e1 = __expf(v1 - m);
                float s = e0 + e1;
                #pragma unroll
                for (int o = 16; o; o >>= 1) s += __shfl_xor_sync(0xffffffffu, s, o);
                float inv = 1.0f / s;
                sl[tid] = e0 * inv;
                sl[tid + 32] = e1 * inv;
            }
            __syncthreads();

            float c = 0.f;
            #pragma unroll 8
            for (int l = 0; l < 64; l++)
                c = fmaf(sl[l], sFEAT[l * 256 + tid], c);
            __half h = __float2half(c);
            g_ctx_hi[b * 256 + tid] = h;
            g_ctx_lo[b * 256 + tid] = __float2half(c - __half2float(h));
        }
        grid_bar2(bid, tid, ++bar);

        // ---- Phase C+D+A': mx = ctx @ gru_k[:256] (mma) + GRU pointwise
        //      + partial hidw2 for next step: st_tile(16x32) @ W2[u0:u0+32,:] ----
        {
            int b0 = (bid >> 4) * 16;
            int u0 = (bid & 15) * 32;
            const uint32_t CTXLO = 8448, WST = 16896, WSZ = 6656;

            auto issueW = [&](int c) {
                uint32_t st = wb + WST + (c & 1) * WSZ;
                int k0 = c * 32;
                #pragma unroll
                for (int i = 0; i < 2; i++) {
                    int idx = tid + (i << 8);
                    if (idx < 384) {
                        int g = idx >> 7, rem = idx & 127, kr = rem >> 2, seg = rem & 3;
                        cpasync16(st + kr * 208 + g * 64 + seg * 16,
                                  g_gk1_h + (size_t)(k0 + kr) * 1536 + g * 512 + u0 + seg * 8, 16);
                    }
                }
            };
            {
                #pragma unroll
                for (int i = 0; i < 4; i++) {
                    int idx = tid + (i << 8);
                    int r = idx >> 6, rem = idx & 63, pl = rem >> 5, seg = rem & 31;
                    const __half* src = (pl ? g_ctx_lo : g_ctx_hi) + (size_t)(b0 + r) * 256 + seg * 8;
                    cpasync16(wb + pl * CTXLO + r * 528 + seg * 16, src, 16);
                }
                issueW(0); CP_COMMIT();
                issueW(1); CP_COMMIT();
            }

            float acc0[4] = {}, acc1[4] = {};
            int tile0 = wid, tile1 = wid + 8;

            for (int c = 0; c < 8; c++) {
                if (c < 7) asm volatile("cp.async.wait_group 1;" ::: "memory");
                else       asm volatile("cp.async.wait_group 0;" ::: "memory");
                __syncthreads();
                uint32_t st = wb + WST + (c & 1) * WSZ;
                #pragma unroll
                for (int ks = 0; ks < 2; ks++) {
                    uint32_t ahi[4], alo[4], bb[2];
                    int row = lane & 15;
                    uint32_t aoff = row * 528 + (c * 32 + ks * 16) * 2 + ((lane >> 4) << 4);
                    ldsm_x4(ahi, wb + aoff);
                    ldsm_x4(alo, wb + CTXLO + aoff);
                    {
                        int g = tile0 >> 2, ns = tile0 & 3;
                        ldsm_x2t(bb, st + (ks * 16 + (lane & 15)) * 208 + g * 64 + ns * 16);
                        mma_f16(acc0, ahi, bb);
                        mma_f16(acc0, alo, bb);
                    }
                    if (wid < 4) {
                        int g = tile1 >> 2, ns = tile1 & 3;
                        ldsm_x2t(bb, st + (ks * 16 + (lane & 15)) * 208 + g * 64 + ns * 16);
                        mma_f16(acc1, ahi, bb);
                        mma_f16(acc1, alo, bb);
                    }
                }
                __syncthreads();
                if (c + 2 < 8) { issueW(c + 2); CP_COMMIT(); }
            }

            __syncthreads();
            float* mxs = work;
            {
                int tr = lane >> 2, tc2 = (lane & 3) * 2;
                {
                    int cb = (tile0 >> 2) * 32 + (tile0 & 3) * 8 + tc2;
                    mxs[tr * 104 + cb] = acc0[0];       mxs[tr * 104 + cb + 1] = acc0[1];
                    mxs[(tr + 8) * 104 + cb] = acc0[2]; mxs[(tr + 8) * 104 + cb + 1] = acc0[3];
                }
                if (wid < 4) {
                    int cb = (tile1 >> 2) * 32 + (tile1 & 3) * 8 + tc2;
                    mxs[tr * 104 + cb] = acc1[0];       mxs[tr * 104 + cb + 1] = acc1[1];
                    mxs[(tr + 8) * 104 + cb] = acc1[2]; mxs[(tr + 8) * 104 + cb + 1] = acc1[3];
                }
            }
            __syncthreads();

            // GRU pointwise -> states (keep fp16 pair in registers for A')
            __half sth[2], stl[2];
            int bl[2], ul2[2];
            #pragma unroll
            for (int i = 0; i < 2; i++) {
                int it = tid + (i << 8);
                int ul = it & 31, b = it >> 5;
                int u = u0 + ul;
                size_t r = (size_t)t * 128 + (b0 + b);
                float xz = mxs[b * 104 + ul]      + g_embmx[r * 1536 + u];
                float xr = mxs[b * 104 + 32 + ul] + g_embmx[r * 1536 + 512 + u];
                float xh = mxs[b * 104 + 64 + ul] + g_embmx[r * 1536 + 1024 + u];
                float rz = gru_b[1536 + u];
                float rr = gru_b[2048 + u];
                float rh = gru_b[2560 + u];
                float z  = 1.f / (1.f + __expf(-(xz + rz)));
                float rg = 1.f / (1.f + __expf(-(xr + rr)));
                float hh = tanh_apx(xh + rg * rh);
                float sv = (1.f - z) * hh;
                __half h = __float2half(sv);
                __half l = __float2half(sv - __half2float(h));
                g_st_hi[r * 512 + u] = h;
                g_st_lo[r * 512 + u] = l;
                sth[i] = h; stl[i] = l; bl[i] = b; ul2[i] = ul;
            }
            __syncthreads();   // mxs reads done; work region free

            // A': P = st_tile @ W2[u0:u0+32,:]  -> g_hidw2p[bid&15]
            __half* stAh = (__half*)work;                      // 16 x 40 halfs (80B rows)
            __half* stAl = (__half*)((char*)work + 1280);
            #pragma unroll
            for (int i = 0; i < 2; i++) {
                stAh[bl[i] * 40 + ul2[i]] = sth[i];
                stAl[bl[i] * 40 + ul2[i]] = stl[i];
            }
            uint32_t wB = wb + 2560 + wid * 2560;   // warp-private 32x32 W2 tile (80B rows)
            auto issueP = [&](int p) {
                #pragma unroll
                for (int s = 0; s < 4; s++) {
                    int ch = lane + s * 32;
                    int r = ch >> 2, seg = ch & 3;
                    cpasync16(wB + r * 80 + seg * 16,
                              g_w2_h + (size_t)(u0 + r) * 512 + p * 256 + wid * 32 + seg * 8, 16);
                }
                CP_COMMIT();
            };
            issueP(0);
            asm volatile("cp.async.wait_group 0;" ::: "memory");
            __syncthreads();   // stA stores + all warps' cp.async visible

            uint32_t sah[2][4], sal[2][4];
            #pragma unroll
            for (int ks = 0; ks < 2; ks++) {
                uint32_t aoff = (lane & 15) * 80 + ks * 32 + ((lane >> 4) << 4);
                ldsm_x4(sah[ks], wb + aoff);
                ldsm_x4(sal[ks], wb + 1280 + aoff);
            }

            float* dstP = g_hidw2p + (size_t)(bid & 15) * 65536 + (size_t)b0 * 512;
            #pragma unroll
            for (int p = 0; p < 2; p++) {
                if (p == 1) {
                    issueP(1);
                    asm volatile("cp.async.wait_group 0;" ::: "memory");
                    __syncwarp();
                }
                float accP[4][4] = {};
                #pragma unroll
                for (int ks = 0; ks < 2; ks++) {
                    #pragma unroll
                    for (int nt = 0; nt < 4; nt++) {
                        uint32_t bb[2];
                        ldsm_x2t(bb, wB + (ks * 16 + (lane & 15)) * 80 + nt * 16);
                        mma_f16(accP[nt], sah[ks], bb);
                        mma_f16(accP[nt], sal[ks], bb);
                    }
                }
                int tr = lane >> 2, tc2 = (lane & 3) * 2;
                #pragma unroll
                for (int nt = 0; nt < 4; nt++) {
                    int col = p * 256 + wid * 32 + nt * 8 + tc2;
                    *(float2*)&dstP[tr * 512 + col] = make_float2(accP[nt][0], accP[nt][1]);
                    *(float2*)&dstP[(tr + 8) * 512 + col] = make_float2(accP[nt][2], accP[nt][3]);
                }
            }
        }
        grid_bar2(bid, tid, ++bar);
    }

    if (bid == 0 && tid == 0) g_epoch = bar0 + (unsigned)(2 * TS);
}

// ---------------- launch ----------------
extern "C" void kernel_launch(void* const* d_in, const int* in_sizes, int n_in,
                              void* d_out, int out_size)
{
    const float* img    = (const float*)d_in[0];
    const int*   target = (const int*)  d_in[1];
    const float* W_fc   = (const float*)d_in[2];
    const float* b_fc   = (const float*)d_in[3];
    const float* W1     = (const float*)d_in[4];
    const float* b1     = (const float*)d_in[5];
    const float* W2     = (const float*)d_in[6];
    const float* b2     = (const float*)d_in[7];
    const float* V      = (const float*)d_in[8];
    const float* bV     = (const float*)d_in[9];
    const float* emb    = (const float*)d_in[10];
    const float* gru_k  = (const float*)d_in[11];
    /* d_in[12] = gru_rk : dead (zero GRU state) */
    const float* gru_b  = (const float*)d_in[13];
    const float* fc1_w  = (const float*)d_in[14];
    const float* fc1_b  = (const float*)d_in[15];
    const float* fc2_w  = (const float*)d_in[16];
    const float* fc2_b  = (const float*)d_in[17];
    float* out = (float*)d_out;

    float *featw1, *features, *embmx;
    __half *imgH, *imgL, *featH, *featL, *etH, *etL, *stH, *stL, *f1oH, *f1oL;
    __half *wfcH, *w1H, *gk2H, *f1wH, *f2wH;
    cudaGetSymbolAddress((void**)&featw1,   g_featw1);
    cudaGetSymbolAddress((void**)&features, g_features);
    cudaGetSymbolAddress((void**)&embmx,    g_embmx);
    cudaGetSymbolAddress((void**)&imgH, g_img_hi);   cudaGetSymbolAddress((void**)&imgL, g_img_lo);
    cudaGetSymbolAddress((void**)&featH, g_feat_hi); cudaGetSymbolAddress((void**)&featL, g_feat_lo);
    cudaGetSymbolAddress((void**)&etH, g_etok_hi);   cudaGetSymbolAddress((void**)&etL, g_etok_lo);
    cudaGetSymbolAddress((void**)&stH, g_st_hi);     cudaGetSymbolAddress((void**)&stL, g_st_lo);
    cudaGetSymbolAddress((void**)&f1oH, g_f1o_hi);   cudaGetSymbolAddress((void**)&f1oL, g_f1o_lo);
    cudaGetSymbolAddress((void**)&wfcH, g_wfc_h);
    cudaGetSymbolAddress((void**)&w1H,  g_w1_h);
    cudaGetSymbolAddress((void**)&gk2H, g_gk2_h);
    cudaGetSymbolAddress((void**)&f1wH, g_f1w_h);
    cudaGetSymbolAddress((void**)&f2wH, g_f2w_h);

    const int SMEM_SZ = 2 * STAGE;   // 58368 B (2-stage, R12-proven)
    cudaFuncSetAttribute(mma_gemm_hf, cudaFuncAttributeMaxDynamicSharedMemorySize, SMEM_SZ);
    const int STEP_SMEM = 56704 * 4; // 226816 B
    cudaFuncSetAttribute(step_loop_kernel, cudaFuncAttributeMaxDynamicSharedMemorySize, STEP_SMEM);

    cvt_fused<<<20804, 256>>>(img, W_fc, W1, gru_k, fc1_w, fc2_w, W2);
    gather_kernel<<<6016, 256>>>(target, emb);
    mma_gemm_hf<<<dim3(2, 64), 256, SMEM_SZ>>>(imgH, imgL, wfcH, b_fc,
                                               features, featH, featL, 8192, 256, 2048, 1, 0);
    mma_gemm_hf<<<dim3(4, 64), 256, SMEM_SZ>>>(featH, featL, w1H, b1,
                                               featw1, nullptr, nullptr, 8192, 512, 256, 0, 0);
    mma_gemm_hf<<<dim3(12, 47), 256, SMEM_SZ>>>(etH, etL, gk2H, gru_b,
                                                embmx, nullptr, nullptr, 6016, 1536, 256, 0, 0);
    step_loop_kernel<<<128, 256, STEP_SMEM>>>(V, bV, b2, gru_b);
    mma_gemm_hf<<<dim3(4, 47), 256, SMEM_SZ>>>(stH, stL, f1wH, fc1_b,
                                               nullptr, f1oH, f1oL, 6016, 512, 512, 0, 0);
    mma_gemm_hf<<<dim3(40, 47), 256, SMEM_SZ>>>(f1oH, f1oL, f2wH, fc2_b,
                                                out, nullptr, nullptr, 6016, 5000, 512, 0, 1);
}

// round 16
// speedup vs baseline: 1.6134x; 1.0052x over previous
#include <cuda_runtime.h>
#include <cuda_fp16.h>
#include <cstdint>

#define TS 47

// ---------------- fp32 scratch ----------------
__device__ __align__(128) float g_featw1 [8192 * 512];
__device__ __align__(128) float g_features[8192 * 256];
__device__ __align__(128) float g_embmx  [6016 * 1536];
__device__ __align__(128) float g_hidw2p [16 * 128 * 512];   // per-u-slice partials

// ---------------- fp16 planes ----------------
__device__ __align__(128) __half g_img_hi [8192 * 2048];
__device__ __align__(128) __half g_feat_hi[8192 * 256],  g_feat_lo[8192 * 256];
__device__ __align__(128) __half g_etok_hi[6016 * 256],  g_etok_lo[6016 * 256];
__device__ __align__(128) __half g_st_hi  [6016 * 512],  g_st_lo  [6016 * 512];
__device__ __align__(128) __half g_f1o_hi [6016 * 512],  g_f1o_lo [6016 * 512];
__device__ __align__(128) __half g_ctx_hi [128 * 256],   g_ctx_lo [128 * 256];
__device__ __align__(128) __half g_wfc_h [2048 * 256];
__device__ __align__(128) __half g_w1_h  [256 * 512];
__device__ __align__(128) __half g_gk1_h [256 * 1536];
__device__ __align__(128) __half g_gk2_h [256 * 1536];
__device__ __align__(128) __half g_w2_h  [512 * 512];
__device__ __align__(128) __half g_f1w_h [512 * 512];
__device__ __align__(128) __half g_f2w_h [512 * 5000];

// ---------------- barrier state (monotonic, replay-safe) ----------------
__device__ unsigned g_flags[128];
__device__ unsigned g_release;
__device__ unsigned g_epoch;

// ---------------- helpers ----------------
__device__ __forceinline__ float tanh_apx(float x) {
    float y;
    asm("tanh.approx.f32 %0, %1;" : "=f"(y) : "f"(x));
    return y;
}
__device__ __forceinline__ unsigned ld_acq(const unsigned* p) {
    unsigned v;
    asm volatile("ld.acquire.gpu.global.u32 %0, [%1];" : "=r"(v) : "l"(p));
    return v;
}
__device__ __forceinline__ void st_rel(unsigned* p, unsigned v) {
    asm volatile("st.release.gpu.global.u32 [%0], %1;" :: "l"(p), "r"(v) : "memory");
}
// two-hop barrier (R12-proven)
__device__ __forceinline__ void grid_bar2(int bid, int tid, unsigned tgt) {
    __syncthreads();
    if (bid == 0) {
        if (tid > 0 && tid < 128) {
            while ((int)(ld_acq(&g_flags[tid]) - tgt) < 0) { }
        }
        __syncthreads();
        if (tid == 0) st_rel(&g_release, tgt);
    } else {
        if (tid == 0) {
            st_rel(&g_flags[bid], tgt);
            while ((int)(ld_acq(&g_release) - tgt) < 0) { }
        }
        __syncthreads();
    }
}
__device__ __forceinline__ uint32_t smem_u32(const void* p) {
    uint32_t a;
    asm("{ .reg .u64 t; cvta.to.shared.u64 t, %1; cvt.u32.u64 %0, t; }"
        : "=r"(a) : "l"(p));
    return a;
}
__device__ __forceinline__ void ldsm_x4(uint32_t* r, uint32_t addr) {
    asm volatile("ldmatrix.sync.aligned.m8n8.x4.shared.b16 {%0,%1,%2,%3}, [%4];"
        : "=r"(r[0]), "=r"(r[1]), "=r"(r[2]), "=r"(r[3]) : "r"(addr));
}
__device__ __forceinline__ void ldsm_x2t(uint32_t* r, uint32_t addr) {
    asm volatile("ldmatrix.sync.aligned.m8n8.x2.trans.shared.b16 {%0,%1}, [%2];"
        : "=r"(r[0]), "=r"(r[1]) : "r"(addr));
}
__device__ __forceinline__ void mma_f16(float* c, const uint32_t* a, const uint32_t* b) {
    asm volatile("mma.sync.aligned.m16n8k16.row.col.f32.f16.f16.f32 "
        "{%0,%1,%2,%3},{%4,%5,%6,%7},{%8,%9},{%0,%1,%2,%3};"
        : "+f"(c[0]), "+f"(c[1]), "+f"(c[2]), "+f"(c[3])
        : "r"(a[0]), "r"(a[1]), "r"(a[2]), "r"(a[3]), "r"(b[0]), "r"(b[1]));
}
__device__ __forceinline__ uint32_t packh(__half a, __half b) {
    __half2 t = __halves2half2(a, b);
    return *(uint32_t*)&t;
}
__device__ __forceinline__ void cpasync16(uint32_t sa, const void* ga, int sz) {
    asm volatile("cp.async.cg.shared.global [%0], [%1], 16, %2;"
                 :: "r"(sa), "l"(ga), "r"(sz) : "memory");
}
#define CP_COMMIT() asm volatile("cp.async.commit_group;" ::: "memory")

// ---------------- fused converts + gather (ONE launch) ----------------
// blocks: img(1-plane) [0,16384) | wfc [,16896) | w1 [,17024) | gk2 [,17408)
//         f1w [,17664) | f2w [,20164) | w2 [,20420) | gk1 [,20804) | gather [,22308)
__global__ void cvt_fused(const float* __restrict__ img, const float* __restrict__ W_fc,
                          const float* __restrict__ W1, const float* __restrict__ gru_k,
                          const float* __restrict__ fc1_w, const float* __restrict__ fc2_w,
                          const float* __restrict__ W2,
                          const int* __restrict__ target, const float* __restrict__ emb)
{
    int blk = blockIdx.x;
    int tid = threadIdx.x;
    if (blk >= 20804) {   // gather -> etok hi/lo pairs
        int r = (blk - 20804) * 4 + (tid >> 6);
        int e4 = (tid & 63) * 4;
        int tt = r >> 7, b = r & 127;
        int tok = (tt == 0) ? 1 : target[b * 48 + tt];
        float4 v = *(const float4*)(emb + (size_t)tok * 256 + e4);
        __half hx = __float2half(v.x), hy = __float2half(v.y);
        __half hz = __float2half(v.z), hw = __float2half(v.w);
        *(uint2*)(g_etok_hi + (size_t)r * 256 + e4) = make_uint2(packh(hx, hy), packh(hz, hw));
        __half lx = __float2half(v.x - __half2float(hx));
        __half ly = __float2half(v.y - __half2float(hy));
        __half lz = __float2half(v.z - __half2float(hz));
        __half lw = __float2half(v.w - __half2float(hw));
        *(uint2*)(g_etok_lo + (size_t)r * 256 + e4) = make_uint2(packh(lx, ly), packh(lz, lw));
        return;
    }
    const float* src;
    __half *one;
    int base;
    if (blk < 16384)      { src = img;              one = g_img_hi; base = blk; }
    else if (blk < 16896) { src = W_fc;             one = g_wfc_h;  base = blk - 16384; }
    else if (blk < 17024) { src = W1;               one = g_w1_h;   base = blk - 16896; }
    else if (blk < 17408) { src = gru_k + 256*1536; one = g_gk2_h;  base = blk - 17024; }
    else if (blk < 17664) { src = fc1_w;            one = g_f1w_h;  base = blk - 17408; }
    else if (blk < 20164) { src = fc2_w;            one = g_f2w_h;  base = blk - 17664; }
    else if (blk < 20420) { src = W2;               one = g_w2_h;   base = blk - 20164; }
    else                  { src = gru_k;            one = g_gk1_h;  base = blk - 20420; }
    int i = (base * 256 + tid) * 4;
    float4 v = *(const float4*)(src + i);
    *(uint2*)(one + i) = make_uint2(packh(__float2half(v.x), __float2half(v.y)),
                                    packh(__float2half(v.z), __float2half(v.w)));
}

// ---------------- fp16 tensor-core GEMM, 2-stage cp.async; ALO = A 2-term split ----------------
#define OFF_ALO 10240
#define OFF_B   20480
#define STAGE   29184

template<bool ALO>
__global__ void __launch_bounds__(256, 2) mma_gemm_hf(
    const __half* __restrict__ Ahi, const __half* __restrict__ Alo,
    const __half* __restrict__ B,
    const float* __restrict__ bias, float* __restrict__ C,
    __half* __restrict__ Chi, __half* __restrict__ Clo,
    int M, int N, int K, int relu, int remap)
{
    extern __shared__ char smem[];
    const int tid = threadIdx.x;
    const int wid = tid >> 5, lane = tid & 31;
    const int bm = blockIdx.y * 128, bn = blockIdx.x * 128;
    const int wm = (wid >> 2) * 64;
    const int wn = (wid & 3) * 32;
    const uint32_t sbase = smem_u32(smem);

    float acc[4][4][4] = {};
    const int nc = K >> 5;

    auto issue = [&](int k0, int s) {
        uint32_t sb = sbase + s * STAGE;
        #pragma unroll
        for (int i = 0; i < 2; i++) {
            int task = tid + (i << 8);
            int m = task >> 2, k8 = (task & 3) << 3;
            uint32_t sa = sb + m * 80 + (k8 << 1);
            size_t go = (size_t)(bm + m) * K + k0 + k8;
            cpasync16(sa, Ahi + go, 16);
            if (ALO) cpasync16(sa + OFF_ALO, Alo + go, 16);
        }
        #pragma unroll
        for (int i = 0; i < 2; i++) {
            int task = tid + (i << 8);
            int kk = task >> 4, n8 = (task & 15) << 3;
            int gc = bn + n8;
            uint32_t sa = sb + OFF_B + kk * 272 + (n8 << 1);
            size_t go = (size_t)(k0 + kk) * N + gc;
            int sz = (gc + 8 <= N) ? 16 : 0;
            cpasync16(sa, B + go, sz);
        }
        CP_COMMIT();
    };

    issue(0, 0);

    for (int c = 0; c < nc; c++) {
        int cur = c & 1;
        if (c + 1 < nc) {
            issue((c + 1) << 5, cur ^ 1);
            asm volatile("cp.async.wait_group 1;" ::: "memory");
        } else {
            asm volatile("cp.async.wait_group 0;" ::: "memory");
        }
        __syncthreads();

        uint32_t base = sbase + cur * STAGE;
        uint32_t aAhi = base, aAlo = base + OFF_ALO;
        uint32_t aB = base + OFF_B;

        #pragma unroll
        for (int kk = 0; kk < 2; kk++) {
            int kb = kk * 16;
            uint32_t ahi[4][4], alo[4][4];
            #pragma unroll
            for (int im = 0; im < 4; im++) {
                int row = wm + im * 16 + (lane & 15);
                uint32_t off = row * 80 + kb * 2 + ((lane >> 4) << 4);
                ldsm_x4(ahi[im], aAhi + off);
                if (ALO) ldsm_x4(alo[im], aAlo + off);
            }
            #pragma unroll
            for (int jn = 0; jn < 4; jn++) {
                int n = wn + jn * 8;
                uint32_t off = (kb + (lane & 15)) * 272 + n * 2;
                uint32_t bb[2];
                ldsm_x2t(bb, aB + off);
                #pragma unroll
                for (int im = 0; im < 4; im++) {
                    mma_f16(acc[im][jn], ahi[im], bb);
                    if (ALO) mma_f16(acc[im][jn], alo[im], bb);
                }
            }
        }
        __syncthreads();
    }

    int tr = lane >> 2, tc = (lane & 3) << 1;
    #pragma unroll
    for (int im = 0; im < 4; im++) {
        #pragma unroll
        for (int half = 0; half < 2; half++) {
            int grow = bm + wm + im * 16 + tr + half * 8;
            size_t ro;
            if (remap) {
                int t = grow >> 7, b = grow & 127;
                ro = ((size_t)b * TS + t) * (size_t)N;
            } else {
                ro = (size_t)grow * (size_t)N;
            }
            #pragma unroll
            for (int jn = 0; jn < 4; jn++) {
                int gc = bn + wn + jn * 8 + tc;
                if (gc < N) {
                    float v0 = acc[im][jn][half * 2 + 0] + bias[gc];
                    float v1 = acc[im][jn][half * 2 + 1] + bias[gc + 1];
                    if (relu) { v0 = fmaxf(v0, 0.f); v1 = fmaxf(v1, 0.f); }
                    if (C) *(float2*)(C + ro + gc) = make_float2(v0, v1);
                    if (Chi) {
                        __half h0 = __float2half(v0);
                        __half h1 = __float2half(v1);
                        *(uint32_t*)(Chi + ro + gc) = packh(h0, h1);
                        __half l0 = __float2half(v0 - __half2float(h0));
                        __half l1 = __float2half(v1 - __half2float(h1));
                        *(uint32_t*)(Clo + ro + gc) = packh(l0, l1);
                    }
                }
            }
        }
    }
}

// ---------------- persistent step loop: 2 barriers/step, A fused into C (R15) ----------------
__global__ __launch_bounds__(256) void step_loop_kernel(
    const float* __restrict__ V, const float* __restrict__ bV,
    const float* __restrict__ b2, const float* __restrict__ gru_b)
{
    extern __shared__ float dsm[];
    float* sFW1  = dsm;
    float* sFEAT = dsm + 32768;
    float* work  = dsm + 49152;

    const int bid = blockIdx.x;
    const int tid = threadIdx.x;
    const int wid = tid >> 5, lane = tid & 31;
    unsigned bar = g_epoch;
    const unsigned bar0 = bar;

    for (int j = tid; j < 8192; j += 256)
        *(float4*)&sFW1[j * 4] = *(const float4*)(g_featw1 + (size_t)bid * 32768 + j * 4);
    for (int j = tid; j < 4096; j += 256)
        *(float4*)&sFEAT[j * 4] = *(const float4*)(g_features + (size_t)bid * 16384 + j * 4);
    __syncthreads();

    const uint32_t wb = smem_u32(work);

    for (int t = 0; t < TS; t++) {
        // ---- Phase B: attention (sums hidw2 partials, float2); emits ctx fp16 pairs ----
        {
            float* hw2 = work;
            float* sV  = work + 512;
            float* sl  = work + 1024;
            int b = bid;
            if (t > 0) {
                int idx2 = tid * 2;
                float2 s = *(const float2*)(b2 + idx2);
                #pragma unroll
                for (int k = 0; k < 16; k++) {
                    float2 p = *(const float2*)(g_hidw2p + (size_t)k * 65536 + b * 512 + idx2);
                    s.x += p.x; s.y += p.y;
                }
                *(float2*)(hw2 + idx2) = s;
            } else {
                hw2[tid]       = b2[tid];
                hw2[tid + 256] = b2[tid + 256];
            }
            sV[tid]       = V[tid];
            sV[tid + 256] = V[tid + 256];
            __syncthreads();

            #pragma unroll
            for (int p = 0; p < 8; p++) {
                int l = wid * 8 + p;
                const float* row = sFW1 + l * 512;
                float a = 0.f;
                #pragma unroll
                for (int j = 0; j < 16; j++) {
                    int u = lane + j * 32;
                    float s = tanh_apx(row[u] + hw2[u]);
                    a = fmaf(s, sV[u], a);
                }
                #pragma unroll
                for (int o = 16; o; o >>= 1) a += __shfl_xor_sync(0xffffffffu, a, o);
                if (lane == 0) sl[l] = a + bV[0];
            }
            __syncthreads();

            if (tid < 32) {
                float v0 = sl[tid], v1 = sl[tid + 32];
                float m = fmaxf(v0, v1);
                #pragma unroll
                for (int o = 16; o; o >>= 1) m = fmaxf(m, __shfl_xor_sync(0xffffffffu, m, o));
                float e0 = __expf(v0 - m), e1 = __expf(v1 - m);
                float s = e0 + e1;
                #pragma unroll
                for (int o = 16; o; o >>= 1) s += __shfl_xor_sync(0xffffffffu, s, o);
                float inv = 1.0f / s;
                sl[tid] = e0 * inv;
                sl[tid + 32] = e1 * inv;
            }
            __syncthreads();

            float c = 0.f;
            #pragma unroll 8
            for (int l = 0; l < 64; l++)
                c = fmaf(sl[l], sFEAT[l * 256 + tid], c);
            __half h = __float2half(c);
            g_ctx_hi[b * 256 + tid] = h;
            g_ctx_lo[b * 256 + tid] = __float2half(c - __half2float(h));
        }
        grid_bar2(bid, tid, ++bar);

        // ---- Phase C+D+A': mx = ctx @ gru_k[:256] + GRU pointwise + partial hidw2 ----
        {
            int b0 = (bid >> 4) * 16;
            int u0 = (bid & 15) * 32;
            const uint32_t CTXLO = 8448, WST = 16896, WSZ = 6656;

            auto issueW = [&](int c) {
                uint32_t st = wb + WST + (c & 1) * WSZ;
                int k0 = c * 32;
                #pragma unroll
                for (int i = 0; i < 2; i++) {
                    int idx = tid + (i << 8);
                    if (idx < 384) {
                        int g = idx >> 7, rem = idx & 127, kr = rem >> 2, seg = rem & 3;
                        cpasync16(st + kr * 208 + g * 64 + seg * 16,
                                  g_gk1_h + (size_t)(k0 + kr) * 1536 + g * 512 + u0 + seg * 8, 16);
                    }
                }
            };
            {
                #pragma unroll
                for (int i = 0; i < 4; i++) {
                    int idx = tid + (i << 8);
                    int r = idx >> 6, rem = idx & 63, pl = rem >> 5, seg = rem & 31;
                    const __half* src = (pl ? g_ctx_lo : g_ctx_hi) + (size_t)(b0 + r) * 256 + seg * 8;
                    cpasync16(wb + pl * CTXLO + r * 528 + seg * 16, src, 16);
                }
                issueW(0); CP_COMMIT();
                issueW(1); CP_COMMIT();
            }

            float acc0[4] = {}, acc1[4] = {};
            int tile0 = wid, tile1 = wid + 8;

            for (int c = 0; c < 8; c++) {
                if (c < 7) asm volatile("cp.async.wait_group 1;" ::: "memory");
                else       asm volatile("cp.async.wait_group 0;" ::: "memory");
                __syncthreads();
                uint32_t st = wb + WST + (c & 1) * WSZ;
                #pragma unroll
                for (int ks = 0; ks < 2; ks++) {
                    uint32_t ahi[4], alo[4], bb[2];
                    int row = lane & 15;
                    uint32_t aoff = row * 528 + (c * 32 + ks * 16) * 2 + ((lane >> 4) << 4);
                    ldsm_x4(ahi, wb + aoff);
                    ldsm_x4(alo, wb + CTXLO + aoff);
                    {
                        int g = tile0 >> 2, ns = tile0 & 3;
                        ldsm_x2t(bb, st + (ks * 16 + (lane & 15)) * 208 + g * 64 + ns * 16);
                        mma_f16(acc0, ahi, bb);
                        mma_f16(acc0, alo, bb);
                    }
                    if (wid < 4) {
                        int g = tile1 >> 2, ns = tile1 & 3;
                        ldsm_x2t(bb, st + (ks * 16 + (lane & 15)) * 208 + g * 64 + ns * 16);
                        mma_f16(acc1, ahi, bb);
                        mma_f16(acc1, alo, bb);
                    }
                }
                __syncthreads();
                if (c + 2 < 8) { issueW(c + 2); CP_COMMIT(); }
            }

            __syncthreads();
            float* mxs = work;
            {
                int tr = lane >> 2, tc2 = (lane & 3) * 2;
                {
                    int cb = (tile0 >> 2) * 32 + (tile0 & 3) * 8 + tc2;
                    mxs[tr * 104 + cb] = acc0[0];       mxs[tr * 104 + cb + 1] = acc0[1];
                    mxs[(tr + 8) * 104 + cb] = acc0[2]; mxs[(tr + 8) * 104 + cb + 1] = acc0[3];
                }
                if (wid < 4) {
                    int cb = (tile1 >> 2) * 32 + (tile1 & 3) * 8 + tc2;
                    mxs[tr * 104 + cb] = acc1[0];       mxs[tr * 104 + cb + 1] = acc1[1];
                    mxs[(tr + 8) * 104 + cb] = acc1[2]; mxs[(tr + 8) * 104 + cb + 1] = acc1[3];
                }
            }
            __syncthreads();

            __half sth[2], stl[2];
            int bl[2], ul2[2];
            #pragma unroll
            for (int i = 0; i < 2; i++) {
                int it = tid + (i << 8);
                int ul = it & 31, b = it >> 5;
                int u = u0 + ul;
                size_t r = (size_t)t * 128 + (b0 + b);
                float xz = mxs[b * 104 + ul]      + g_embmx[r * 1536 + u];
                float xr = mxs[b * 104 + 32 + ul] + g_embmx[r * 1536 + 512 + u];
                float xh = mxs[b * 104 + 64 + ul] + g_embmx[r * 1536 + 1024 + u];
                float rz = gru_b[1536 + u];
                float rr = gru_b[2048 + u];
                float rh = gru_b[2560 + u];
                float z  = 1.f / (1.f + __expf(-(xz + rz)));
                float rg = 1.f / (1.f + __expf(-(xr + rr)));
                float hh = tanh_apx(xh + rg * rh);
                float sv = (1.f - z) * hh;
                __half h = __float2half(sv);
                __half l = __float2half(sv - __half2float(h));
                g_st_hi[r * 512 + u] = h;
                g_st_lo[r * 512 + u] = l;
                sth[i] = h; stl[i] = l; bl[i] = b; ul2[i] = ul;
            }
            __syncthreads();

            __half* stAh = (__half*)work;
            __half* stAl = (__half*)((char*)work + 1280);
            #pragma unroll
            for (int i = 0; i < 2; i++) {
                stAh[bl[i] * 40 + ul2[i]] = sth[i];
                stAl[bl[i] * 40 + ul2[i]] = stl[i];
            }
            uint32_t wB = wb + 2560 + wid * 2560;
            auto issueP = [&](int p) {
                #pragma unroll
                for (int s = 0; s < 4; s++) {
                    int ch = lane + s * 32;
                    int r = ch >> 2, seg = ch & 3;
                    cpasync16(wB + r * 80 + seg * 16,
                              g_w2_h + (size_t)(u0 + r) * 512 + p * 256 + wid * 32 + seg * 8, 16);
                }
                CP_COMMIT();
            };
            issueP(0);
            asm volatile("cp.async.wait_group 0;" ::: "memory");
            __syncthreads();

            uint32_t sah[2][4], sal[2][4];
            #pragma unroll
            for (int ks = 0; ks < 2; ks++) {
                uint32_t aoff = (lane & 15) * 80 + ks * 32 + ((lane >> 4) << 4);
                ldsm_x4(sah[ks], wb + aoff);
                ldsm_x4(sal[ks], wb + 1280 + aoff);
            }

            float* dstP = g_hidw2p + (size_t)(bid & 15) * 65536 + (size_t)b0 * 512;
            #pragma unroll
            for (int p = 0; p < 2; p++) {
                if (p == 1) {
                    issueP(1);
                    asm volatile("cp.async.wait_group 0;" ::: "memory");
                    __syncwarp();
                }
                float accP[4][4] = {};
                #pragma unroll
                for (int ks = 0; ks < 2; ks++) {
                    #pragma unroll
                    for (int nt = 0; nt < 4; nt++) {
                        uint32_t bb[2];
                        ldsm_x2t(bb, wB + (ks * 16 + (lane & 15)) * 80 + nt * 16);
                        mma_f16(accP[nt], sah[ks], bb);
                        mma_f16(accP[nt], sal[ks], bb);
                    }
                }
                int tr = lane >> 2, tc2 = (lane & 3) * 2;
                #pragma unroll
                for (int nt = 0; nt < 4; nt++) {
                    int col = p * 256 + wid * 32 + nt * 8 + tc2;
                    *(float2*)&dstP[tr * 512 + col] = make_float2(accP[nt][0], accP[nt][1]);
                    *(float2*)&dstP[(tr + 8) * 512 + col] = make_float2(accP[nt][2], accP[nt][3]);
                }
            }
        }
        grid_bar2(bid, tid, ++bar);
    }

    if (bid == 0 && tid == 0) g_epoch = bar0 + (unsigned)(2 * TS);
}

// ---------------- launch ----------------
extern "C" void kernel_launch(void* const* d_in, const int* in_sizes, int n_in,
                              void* d_out, int out_size)
{
    const float* img    = (const float*)d_in[0];
    const int*   target = (const int*)  d_in[1];
    const float* W_fc   = (const float*)d_in[2];
    const float* b_fc   = (const float*)d_in[3];
    const float* W1     = (const float*)d_in[4];
    const float* b1     = (const float*)d_in[5];
    const float* W2     = (const float*)d_in[6];
    const float* b2     = (const float*)d_in[7];
    const float* V      = (const float*)d_in[8];
    const float* bV     = (const float*)d_in[9];
    const float* emb    = (const float*)d_in[10];
    const float* gru_k  = (const float*)d_in[11];
    /* d_in[12] = gru_rk : dead (zero GRU state) */
    const float* gru_b  = (const float*)d_in[13];
    const float* fc1_w  = (const float*)d_in[14];
    const float* fc1_b  = (const float*)d_in[15];
    const float* fc2_w  = (const float*)d_in[16];
    const float* fc2_b  = (const float*)d_in[17];
    float* out = (float*)d_out;

    float *featw1, *features, *embmx;
    __half *imgH, *featH, *featL, *etH, *etL, *stH, *stL, *f1oH, *f1oL;
    __half *wfcH, *w1H, *gk2H, *f1wH, *f2wH;
    cudaGetSymbolAddress((void**)&featw1,   g_featw1);
    cudaGetSymbolAddress((void**)&features, g_features);
    cudaGetSymbolAddress((void**)&embmx,    g_embmx);
    cudaGetSymbolAddress((void**)&imgH, g_img_hi);
    cudaGetSymbolAddress((void**)&featH, g_feat_hi); cudaGetSymbolAddress((void**)&featL, g_feat_lo);
    cudaGetSymbolAddress((void**)&etH, g_etok_hi);   cudaGetSymbolAddress((void**)&etL, g_etok_lo);
    cudaGetSymbolAddress((void**)&stH, g_st_hi);     cudaGetSymbolAddress((void**)&stL, g_st_lo);
    cudaGetSymbolAddress((void**)&f1oH, g_f1o_hi);   cudaGetSymbolAddress((void**)&f1oL, g_f1o_lo);
    cudaGetSymbolAddress((void**)&wfcH, g_wfc_h);
    cudaGetSymbolAddress((void**)&w1H,  g_w1_h);
    cudaGetSymbolAddress((void**)&gk2H, g_gk2_h);
    cudaGetSymbolAddress((void**)&f1wH, g_f1w_h);
    cudaGetSymbolAddress((void**)&f2wH, g_f2w_h);

    const int SMEM_SZ = 2 * STAGE;   // 58368 B
    cudaFuncSetAttribute(mma_gemm_hf<true>,  cudaFuncAttributeMaxDynamicSharedMemorySize, SMEM_SZ);
    cudaFuncSetAttribute(mma_gemm_hf<false>, cudaFuncAttributeMaxDynamicSharedMemorySize, SMEM_SZ);
    const int STEP_SMEM = 56704 * 4; // 226816 B
    cudaFuncSetAttribute(step_loop_kernel, cudaFuncAttributeMaxDynamicSharedMemorySize, STEP_SMEM);

    // launch 0: all converts + gather in ONE kernel
    cvt_fused<<<22308, 256>>>(img, W_fc, W1, gru_k, fc1_w, fc2_w, W2, target, emb);
    // encoder (A single-term): features = relu(img @ W_fc + b_fc)
    mma_gemm_hf<false><<<dim3(2, 64), 256, SMEM_SZ>>>(imgH, nullptr, wfcH, b_fc,
                                                      features, featH, featL, 8192, 256, 2048, 1, 0);
    // featw1 = features @ W1 + b1
    mma_gemm_hf<true><<<dim3(4, 64), 256, SMEM_SZ>>>(featH, featL, w1H, b1,
                                                     featw1, nullptr, nullptr, 8192, 512, 256, 0, 0);
    // embmx = embtok @ gru_k[256:] + gru_b[0]
    mma_gemm_hf<true><<<dim3(12, 47), 256, SMEM_SZ>>>(etH, etL, gk2H, gru_b,
                                                      embmx, nullptr, nullptr, 6016, 1536, 256, 0, 0);
    // persistent step loop
    step_loop_kernel<<<128, 256, STEP_SMEM>>>(V, bV, b2, gru_b);
    // fc1 / fc2
    mma_gemm_hf<true><<<dim3(4, 47), 256, SMEM_SZ>>>(stH, stL, f1wH, fc1_b,
                                                     nullptr, f1oH, f1oL, 6016, 512, 512, 0, 0);
    mma_gemm_hf<true><<<dim3(40, 47), 256, SMEM_SZ>>>(f1oH, f1oL, f2wH, fc2_b,
                                                      out, nullptr, nullptr, 6016, 5000, 512, 0, 1);
}

// round 17
// speedup vs baseline: 1.8308x; 1.1347x over previous
#include <cuda_runtime.h>
#include <cuda_fp16.h>
#include <cstdint>

#define TS 47

// ---------------- fp32 scratch ----------------
__device__ __align__(128) float g_featw1 [8192 * 512];
__device__ __align__(128) float g_features[8192 * 256];
__device__ __align__(128) float g_embmx  [6016 * 1536];
__device__ __align__(128) float g_hidw2p [16 * 128 * 512];   // per-u-slice partials

// ---------------- fp16 planes ----------------
__device__ __align__(128) __half g_img_hi [8192 * 2048];
__device__ __align__(128) __half g_feat_hi[8192 * 256];
__device__ __align__(128) __half g_etok_hi[6016 * 256];
__device__ __align__(128) __half g_st_hi  [6016 * 512],  g_st_lo  [6016 * 512];
__device__ __align__(128) __half g_f1o_hi [6016 * 512];
__device__ __align__(128) __half g_ctx_hi [128 * 256],   g_ctx_lo [128 * 256];
__device__ __align__(128) __half g_wfc_h [2048 * 256];
__device__ __align__(128) __half g_w1_h  [256 * 512];
__device__ __align__(128) __half g_gk1_h [256 * 1536];
__device__ __align__(128) __half g_gk2_h [256 * 1536];
__device__ __align__(128) __half g_w2_h  [512 * 512];
__device__ __align__(128) __half g_f1w_h [512 * 512];
__device__ __align__(128) __half g_f2w_h [512 * 5000];

// ---------------- barrier state (monotonic, replay-safe) ----------------
__device__ unsigned g_flags[128];
__device__ unsigned g_release;
__device__ unsigned g_epoch;

// ---------------- helpers ----------------
__device__ __forceinline__ float tanh_apx(float x) {
    float y;
    asm("tanh.approx.f32 %0, %1;" : "=f"(y) : "f"(x));
    return y;
}
__device__ __forceinline__ unsigned ld_acq(const unsigned* p) {
    unsigned v;
    asm volatile("ld.acquire.gpu.global.u32 %0, [%1];" : "=r"(v) : "l"(p));
    return v;
}
__device__ __forceinline__ void st_rel(unsigned* p, unsigned v) {
    asm volatile("st.release.gpu.global.u32 [%0], %1;" :: "l"(p), "r"(v) : "memory");
}
// two-hop barrier (R12-proven)
__device__ __forceinline__ void grid_bar2(int bid, int tid, unsigned tgt) {
    __syncthreads();
    if (bid == 0) {
        if (tid > 0 && tid < 128) {
            while ((int)(ld_acq(&g_flags[tid]) - tgt) < 0) { }
        }
        __syncthreads();
        if (tid == 0) st_rel(&g_release, tgt);
    } else {
        if (tid == 0) {
            st_rel(&g_flags[bid], tgt);
            while ((int)(ld_acq(&g_release) - tgt) < 0) { }
        }
        __syncthreads();
    }
}
__device__ __forceinline__ uint32_t smem_u32(const void* p) {
    uint32_t a;
    asm("{ .reg .u64 t; cvta.to.shared.u64 t, %1; cvt.u32.u64 %0, t; }"
        : "=r"(a) : "l"(p));
    return a;
}
__device__ __forceinline__ void ldsm_x4(uint32_t* r, uint32_t addr) {
    asm volatile("ldmatrix.sync.aligned.m8n8.x4.shared.b16 {%0,%1,%2,%3}, [%4];"
        : "=r"(r[0]), "=r"(r[1]), "=r"(r[2]), "=r"(r[3]) : "r"(addr));
}
__device__ __forceinline__ void ldsm_x2t(uint32_t* r, uint32_t addr) {
    asm volatile("ldmatrix.sync.aligned.m8n8.x2.trans.shared.b16 {%0,%1}, [%2];"
        : "=r"(r[0]), "=r"(r[1]) : "r"(addr));
}
__device__ __forceinline__ void mma_f16(float* c, const uint32_t* a, const uint32_t* b) {
    asm volatile("mma.sync.aligned.m16n8k16.row.col.f32.f16.f16.f32 "
        "{%0,%1,%2,%3},{%4,%5,%6,%7},{%8,%9},{%0,%1,%2,%3};"
        : "+f"(c[0]), "+f"(c[1]), "+f"(c[2]), "+f"(c[3])
        : "r"(a[0]), "r"(a[1]), "r"(a[2]), "r"(a[3]), "r"(b[0]), "r"(b[1]));
}
__device__ __forceinline__ uint32_t packh(__half a, __half b) {
    __half2 t = __halves2half2(a, b);
    return *(uint32_t*)&t;
}
__device__ __forceinline__ void cpasync16(uint32_t sa, const void* ga, int sz) {
    asm volatile("cp.async.cg.shared.global [%0], [%1], 16, %2;"
                 :: "r"(sa), "l"(ga), "r"(sz) : "memory");
}
#define CP_COMMIT() asm volatile("cp.async.commit_group;" ::: "memory")

// ---------------- fused converts + gather (ONE launch) ----------------
__global__ void cvt_fused(const float* __restrict__ img, const float* __restrict__ W_fc,
                          const float* __restrict__ W1, const float* __restrict__ gru_k,
                          const float* __restrict__ fc1_w, const float* __restrict__ fc2_w,
                          const float* __restrict__ W2,
                          const int* __restrict__ target, const float* __restrict__ emb)
{
    int blk = blockIdx.x;
    int tid = threadIdx.x;
    if (blk >= 20804) {   // gather -> etok hi plane only
        int r = (blk - 20804) * 4 + (tid >> 6);
        int e4 = (tid & 63) * 4;
        int tt = r >> 7, b = r & 127;
        int tok = (tt == 0) ? 1 : target[b * 48 + tt];
        float4 v = *(const float4*)(emb + (size_t)tok * 256 + e4);
        *(uint2*)(g_etok_hi + (size_t)r * 256 + e4) =
            make_uint2(packh(__float2half(v.x), __float2half(v.y)),
                       packh(__float2half(v.z), __float2half(v.w)));
        return;
    }
    const float* src;
    __half *one;
    int base;
    if (blk < 16384)      { src = img;              one = g_img_hi; base = blk; }
    else if (blk < 16896) { src = W_fc;             one = g_wfc_h;  base = blk - 16384; }
    else if (blk < 17024) { src = W1;               one = g_w1_h;   base = blk - 16896; }
    else if (blk < 17408) { src = gru_k + 256*1536; one = g_gk2_h;  base = blk - 17024; }
    else if (blk < 17664) { src = fc1_w;            one = g_f1w_h;  base = blk - 17408; }
    else if (blk < 20164) { src = fc2_w;            one = g_f2w_h;  base = blk - 17664; }
    else if (blk < 20420) { src = W2;               one = g_w2_h;   base = blk - 20164; }
    else                  { src = gru_k;            one = g_gk1_h;  base = blk - 20420; }
    int i = (base * 256 + tid) * 4;
    float4 v = *(const float4*)(src + i);
    *(uint2*)(one + i) = make_uint2(packh(__float2half(v.x), __float2half(v.y)),
                                    packh(__float2half(v.z), __float2half(v.w)));
}

// ---------------- fp16 tensor-core GEMM, 2-stage cp.async; ALO = A 2-term split ----------------
#define OFF_ALO 10240
#define OFF_B   20480
#define STAGE   29184

template<bool ALO>
__global__ void __launch_bounds__(256, 2) mma_gemm_hf(
    const __half* __restrict__ Ahi, const __half* __restrict__ Alo,
    const __half* __restrict__ B,
    const float* __restrict__ bias, float* __restrict__ C,
    __half* __restrict__ Chi, __half* __restrict__ Clo,
    int M, int N, int K, int relu, int remap)
{
    extern __shared__ char smem[];
    const int tid = threadIdx.x;
    const int wid = tid >> 5, lane = tid & 31;
    const int bm = blockIdx.y * 128, bn = blockIdx.x * 128;
    const int wm = (wid >> 2) * 64;
    const int wn = (wid & 3) * 32;
    const uint32_t sbase = smem_u32(smem);

    float acc[4][4][4] = {};
    const int nc = K >> 5;

    auto issue = [&](int k0, int s) {
        uint32_t sb = sbase + s * STAGE;
        #pragma unroll
        for (int i = 0; i < 2; i++) {
            int task = tid + (i << 8);
            int m = task >> 2, k8 = (task & 3) << 3;
            uint32_t sa = sb + m * 80 + (k8 << 1);
            size_t go = (size_t)(bm + m) * K + k0 + k8;
            cpasync16(sa, Ahi + go, 16);
            if (ALO) cpasync16(sa + OFF_ALO, Alo + go, 16);
        }
        #pragma unroll
        for (int i = 0; i < 2; i++) {
            int task = tid + (i << 8);
            int kk = task >> 4, n8 = (task & 15) << 3;
            int gc = bn + n8;
            uint32_t sa = sb + OFF_B + kk * 272 + (n8 << 1);
            size_t go = (size_t)(k0 + kk) * N + gc;
            int sz = (gc + 8 <= N) ? 16 : 0;
            cpasync16(sa, B + go, sz);
        }
        CP_COMMIT();
    };

    issue(0, 0);

    for (int c = 0; c < nc; c++) {
        int cur = c & 1;
        if (c + 1 < nc) {
            issue((c + 1) << 5, cur ^ 1);
            asm volatile("cp.async.wait_group 1;" ::: "memory");
        } else {
            asm volatile("cp.async.wait_group 0;" ::: "memory");
        }
        __syncthreads();

        uint32_t base = sbase + cur * STAGE;
        uint32_t aAhi = base, aAlo = base + OFF_ALO;
        uint32_t aB = base + OFF_B;

        #pragma unroll
        for (int kk = 0; kk < 2; kk++) {
            int kb = kk * 16;
            uint32_t ahi[4][4], alo[4][4];
            #pragma unroll
            for (int im = 0; im < 4; im++) {
                int row = wm + im * 16 + (lane & 15);
                uint32_t off = row * 80 + kb * 2 + ((lane >> 4) << 4);
                ldsm_x4(ahi[im], aAhi + off);
                if (ALO) ldsm_x4(alo[im], aAlo + off);
            }
            #pragma unroll
            for (int jn = 0; jn < 4; jn++) {
                int n = wn + jn * 8;
                uint32_t off = (kb + (lane & 15)) * 272 + n * 2;
                uint32_t bb[2];
                ldsm_x2t(bb, aB + off);
                #pragma unroll
                for (int im = 0; im < 4; im++) {
                    mma_f16(acc[im][jn], ahi[im], bb);
                    if (ALO) mma_f16(acc[im][jn], alo[im], bb);
                }
            }
        }
        __syncthreads();
    }

    int tr = lane >> 2, tc = (lane & 3) << 1;
    #pragma unroll
    for (int im = 0; im < 4; im++) {
        #pragma unroll
        for (int half = 0; half < 2; half++) {
            int grow = bm + wm + im * 16 + tr + half * 8;
            size_t ro;
            if (remap) {
                int t = grow >> 7, b = grow & 127;
                ro = ((size_t)b * TS + t) * (size_t)N;
            } else {
                ro = (size_t)grow * (size_t)N;
            }
            #pragma unroll
            for (int jn = 0; jn < 4; jn++) {
                int gc = bn + wn + jn * 8 + tc;
                if (gc < N) {
                    float v0 = acc[im][jn][half * 2 + 0] + bias[gc];
                    float v1 = acc[im][jn][half * 2 + 1] + bias[gc + 1];
                    if (relu) { v0 = fmaxf(v0, 0.f); v1 = fmaxf(v1, 0.f); }
                    if (C) *(float2*)(C + ro + gc) = make_float2(v0, v1);
                    if (Chi) {
                        __half h0 = __float2half(v0);
                        __half h1 = __float2half(v1);
                        *(uint32_t*)(Chi + ro + gc) = packh(h0, h1);
                        if (Clo) {
                            __half l0 = __float2half(v0 - __half2float(h0));
                            __half l1 = __float2half(v1 - __half2float(h1));
                            *(uint32_t*)(Clo + ro + gc) = packh(l0, l1);
                        }
                    }
                }
            }
        }
    }
}

// ---------------- persistent step loop: 2 barriers/step, A fused into C (R15) ----------------
__global__ __launch_bounds__(256) void step_loop_kernel(
    const float* __restrict__ V, const float* __restrict__ bV,
    const float* __restrict__ b2, const float* __restrict__ gru_b)
{
    extern __shared__ float dsm[];
    float* sFW1  = dsm;
    float* sFEAT = dsm + 32768;
    float* work  = dsm + 49152;

    const int bid = blockIdx.x;
    const int tid = threadIdx.x;
    const int wid = tid >> 5, lane = tid & 31;
    unsigned bar = g_epoch;
    const unsigned bar0 = bar;

    for (int j = tid; j < 8192; j += 256)
        *(float4*)&sFW1[j * 4] = *(const float4*)(g_featw1 + (size_t)bid * 32768 + j * 4);
    for (int j = tid; j < 4096; j += 256)
        *(float4*)&sFEAT[j * 4] = *(const float4*)(g_features + (size_t)bid * 16384 + j * 4);
    __syncthreads();

    const uint32_t wb = smem_u32(work);

    for (int t = 0; t < TS; t++) {
        // ---- Phase B: attention (sums hidw2 partials, float2); emits ctx fp16 pairs ----
        {
            float* hw2 = work;
            float* sV  = work + 512;
            float* sl  = work + 1024;
            int b = bid;
            if (t > 0) {
                int idx2 = tid * 2;
                float2 s = *(const float2*)(b2 + idx2);
                #pragma unroll
                for (int k = 0; k < 16; k++) {
                    float2 p = *(const float2*)(g_hidw2p + (size_t)k * 65536 + b * 512 + idx2);
                    s.x += p.x; s.y += p.y;
                }
                *(float2*)(hw2 + idx2) = s;
            } else {
                hw2[tid]       = b2[tid];
                hw2[tid + 256] = b2[tid + 256];
            }
            sV[tid]       = V[tid];
            sV[tid + 256] = V[tid + 256];
            __syncthreads();

            #pragma unroll
            for (int p = 0; p < 8; p++) {
                int l = wid * 8 + p;
                const float* row = sFW1 + l * 512;
                float a = 0.f;
                #pragma unroll
                for (int j = 0; j < 16; j++) {
                    int u = lane + j * 32;
                    float s = tanh_apx(row[u] + hw2[u]);
                    a = fmaf(s, sV[u], a);
                }
                #pragma unroll
                for (int o = 16; o; o >>= 1) a += __shfl_xor_sync(0xffffffffu, a, o);
                if (lane == 0) sl[l] = a + bV[0];
            }
            __syncthreads();

            if (tid < 32) {
                float v0 = sl[tid], v1 = sl[tid + 32];
                float m = fmaxf(v0, v1);
                #pragma unroll
                for (int o = 16; o; o >>= 1) m = fmaxf(m, __shfl_xor_sync(0xffffffffu, m, o));
                float e0 = __expf(v0 - m), e1 = __expf(v1 - m);
                float s = e0 + e1;
                #pragma unroll
                for (int o = 16; o; o >>= 1) s += __shfl_xor_sync(0xffffffffu, s, o);
                float inv = 1.0f / s;
                sl[tid] = e0 * inv;
                sl[tid + 32] = e1 * inv;
            }
            __syncthreads();

            float c = 0.f;
            #pragma unroll 8
            for (int l = 0; l < 64; l++)
                c = fmaf(sl[l], sFEAT[l * 256 + tid], c);
            __half h = __float2half(c);
            g_ctx_hi[b * 256 + tid] = h;
            g_ctx_lo[b * 256 + tid] = __float2half(c - __half2float(h));
        }
        grid_bar2(bid, tid, ++bar);

        // ---- Phase C+D+A': mx = ctx @ gru_k[:256] + GRU pointwise + partial hidw2 ----
        {
            int b0 = (bid >> 4) * 16;
            int u0 = (bid & 15) * 32;
            const uint32_t CTXLO = 8448, WST = 16896, WSZ = 6656;

            auto issueW = [&](int c) {
                uint32_t st = wb + WST + (c & 1) * WSZ;
                int k0 = c * 32;
                #pragma unroll
                for (int i = 0; i < 2; i++) {
                    int idx = tid + (i << 8);
                    if (idx < 384) {
                        int g = idx >> 7, rem = idx & 127, kr = rem >> 2, seg = rem & 3;
                        cpasync16(st + kr * 208 + g * 64 + seg * 16,
                                  g_gk1_h + (size_t)(k0 + kr) * 1536 + g * 512 + u0 + seg * 8, 16);
                    }
                }
            };
            {
                #pragma unroll
                for (int i = 0; i < 4; i++) {
                    int idx = tid + (i << 8);
                    int r = idx >> 6, rem = idx & 63, pl = rem >> 5, seg = rem & 31;
                    const __half* src = (pl ? g_ctx_lo : g_ctx_hi) + (size_t)(b0 + r) * 256 + seg * 8;
                    cpasync16(wb + pl * CTXLO + r * 528 + seg * 16, src, 16);
                }
                issueW(0); CP_COMMIT();
                issueW(1); CP_COMMIT();
            }

            float acc0[4] = {}, acc1[4] = {};
            int tile0 = wid, tile1 = wid + 8;

            for (int c = 0; c < 8; c++) {
                if (c < 7) asm volatile("cp.async.wait_group 1;" ::: "memory");
                else       asm volatile("cp.async.wait_group 0;" ::: "memory");
                __syncthreads();
                uint32_t st = wb + WST + (c & 1) * WSZ;
                #pragma unroll
                for (int ks = 0; ks < 2; ks++) {
                    uint32_t ahi[4], alo[4], bb[2];
                    int row = lane & 15;
                    uint32_t aoff = row * 528 + (c * 32 + ks * 16) * 2 + ((lane >> 4) << 4);
                    ldsm_x4(ahi, wb + aoff);
                    ldsm_x4(alo, wb + CTXLO + aoff);
                    {
                        int g = tile0 >> 2, ns = tile0 & 3;
                        ldsm_x2t(bb, st + (ks * 16 + (lane & 15)) * 208 + g * 64 + ns * 16);
                        mma_f16(acc0, ahi, bb);
                        mma_f16(acc0, alo, bb);
                    }
                    if (wid < 4) {
                        int g = tile1 >> 2, ns = tile1 & 3;
                        ldsm_x2t(bb, st + (ks * 16 + (lane & 15)) * 208 + g * 64 + ns * 16);
                        mma_f16(acc1, ahi, bb);
                        mma_f16(acc1, alo, bb);
                    }
                }
                __syncthreads();
                if (c + 2 < 8) { issueW(c + 2); CP_COMMIT(); }
            }

            __syncthreads();
            float* mxs = work;
            {
                int tr = lane >> 2, tc2 = (lane & 3) * 2;
                {
                    int cb = (tile0 >> 2) * 32 + (tile0 & 3) * 8 + tc2;
                    mxs[tr * 104 + cb] = acc0[0];       mxs[tr * 104 + cb + 1] = acc0[1];
                    mxs[(tr + 8) * 104 + cb] = acc0[2]; mxs[(tr + 8) * 104 + cb + 1] = acc0[3];
                }
                if (wid < 4) {
                    int cb = (tile1 >> 2) * 32 + (tile1 & 3) * 8 + tc2;
                    mxs[tr * 104 + cb] = acc1[0];       mxs[tr * 104 + cb + 1] = acc1[1];
                    mxs[(tr + 8) * 104 + cb] = acc1[2]; mxs[(tr + 8) * 104 + cb + 1] = acc1[3];
                }
            }
            __syncthreads();

            __half sth[2], stl[2];
            int bl[2], ul2[2];
            #pragma unroll
            for (int i = 0; i < 2; i++) {
                int it = tid + (i << 8);
                int ul = it & 31, b = it >> 5;
                int u = u0 + ul;
                size_t r = (size_t)t * 128 + (b0 + b);
                float xz = mxs[b * 104 + ul]      + g_embmx[r * 1536 + u];
                float xr = mxs[b * 104 + 32 + ul] + g_embmx[r * 1536 + 512 + u];
                float xh = mxs[b * 104 + 64 + ul] + g_embmx[r * 1536 + 1024 + u];
                float rz = gru_b[1536 + u];
                float rr = gru_b[2048 + u];
                float rh = gru_b[2560 + u];
                float z  = 1.f / (1.f + __expf(-(xz + rz)));
                float rg = 1.f / (1.f + __expf(-(xr + rr)));
                float hh = tanh_apx(xh + rg * rh);
                float sv = (1.f - z) * hh;
                __half h = __float2half(sv);
                __half l = __float2half(sv - __half2float(h));
                g_st_hi[r * 512 + u] = h;
                g_st_lo[r * 512 + u] = l;
                sth[i] = h; stl[i] = l; bl[i] = b; ul2[i] = ul;
            }
            __syncthreads();

            __half* stAh = (__half*)work;
            __half* stAl = (__half*)((char*)work + 1280);
            #pragma unroll
            for (int i = 0; i < 2; i++) {
                stAh[bl[i] * 40 + ul2[i]] = sth[i];
                stAl[bl[i] * 40 + ul2[i]] = stl[i];
            }
            uint32_t wB = wb + 2560 + wid * 2560;
            auto issueP = [&](int p) {
                #pragma unroll
                for (int s = 0; s < 4; s++) {
                    int ch = lane + s * 32;
                    int r = ch >> 2, seg = ch & 3;
                    cpasync16(wB + r * 80 + seg * 16,
                              g_w2_h + (size_t)(u0 + r) * 512 + p * 256 + wid * 32 + seg * 8, 16);
                }
                CP_COMMIT();
            };
            issueP(0);
            asm volatile("cp.async.wait_group 0;" ::: "memory");
            __syncthreads();

            uint32_t sah[2][4], sal[2][4];
            #pragma unroll
            for (int ks = 0; ks < 2; ks++) {
                uint32_t aoff = (lane & 15) * 80 + ks * 32 + ((lane >> 4) << 4);
                ldsm_x4(sah[ks], wb + aoff);
                ldsm_x4(sal[ks], wb + 1280 + aoff);
            }

            float* dstP = g_hidw2p + (size_t)(bid & 15) * 65536 + (size_t)b0 * 512;
            #pragma unroll
            for (int p = 0; p < 2; p++) {
                if (p == 1) {
                    issueP(1);
                    asm volatile("cp.async.wait_group 0;" ::: "memory");
                    __syncwarp();
                }
                float accP[4][4] = {};
                #pragma unroll
                for (int ks = 0; ks < 2; ks++) {
                    #pragma unroll
                    for (int nt = 0; nt < 4; nt++) {
                        uint32_t bb[2];
                        ldsm_x2t(bb, wB + (ks * 16 + (lane & 15)) * 80 + nt * 16);
                        mma_f16(accP[nt], sah[ks], bb);
                        mma_f16(accP[nt], sal[ks], bb);
                    }
                }
                int tr = lane >> 2, tc2 = (lane & 3) * 2;
                #pragma unroll
                for (int nt = 0; nt < 4; nt++) {
                    int col = p * 256 + wid * 32 + nt * 8 + tc2;
                    *(float2*)&dstP[tr * 512 + col] = make_float2(accP[nt][0], accP[nt][1]);
                    *(float2*)&dstP[(tr + 8) * 512 + col] = make_float2(accP[nt][2], accP[nt][3]);
                }
            }
        }
        grid_bar2(bid, tid, ++bar);
    }

    if (bid == 0 && tid == 0) g_epoch = bar0 + (unsigned)(2 * TS);
}

// ---------------- launch ----------------
extern "C" void kernel_launch(void* const* d_in, const int* in_sizes, int n_in,
                              void* d_out, int out_size)
{
    const float* img    = (const float*)d_in[0];
    const int*   target = (const int*)  d_in[1];
    const float* W_fc   = (const float*)d_in[2];
    const float* b_fc   = (const float*)d_in[3];
    const float* W1     = (const float*)d_in[4];
    const float* b1     = (const float*)d_in[5];
    const float* W2     = (const float*)d_in[6];
    const float* b2     = (const float*)d_in[7];
    const float* V      = (const float*)d_in[8];
    const float* bV     = (const float*)d_in[9];
    const float* emb    = (const float*)d_in[10];
    const float* gru_k  = (const float*)d_in[11];
    /* d_in[12] = gru_rk : dead (zero GRU state) */
    const float* gru_b  = (const float*)d_in[13];
    const float* fc1_w  = (const float*)d_in[14];
    const float* fc1_b  = (const float*)d_in[15];
    const float* fc2_w  = (const float*)d_in[16];
    const float* fc2_b  = (const float*)d_in[17];
    float* out = (float*)d_out;

    float *featw1, *features, *embmx;
    __half *imgH, *featH, *etH, *stH, *stL, *f1oH;
    __half *wfcH, *w1H, *gk2H, *f1wH, *f2wH;
    cudaGetSymbolAddress((void**)&featw1,   g_featw1);
    cudaGetSymbolAddress((void**)&features, g_features);
    cudaGetSymbolAddress((void**)&embmx,    g_embmx);
    cudaGetSymbolAddress((void**)&imgH, g_img_hi);
    cudaGetSymbolAddress((void**)&featH, g_feat_hi);
    cudaGetSymbolAddress((void**)&etH, g_etok_hi);
    cudaGetSymbolAddress((void**)&stH, g_st_hi);     cudaGetSymbolAddress((void**)&stL, g_st_lo);
    cudaGetSymbolAddress((void**)&f1oH, g_f1o_hi);
    cudaGetSymbolAddress((void**)&wfcH, g_wfc_h);
    cudaGetSymbolAddress((void**)&w1H,  g_w1_h);
    cudaGetSymbolAddress((void**)&gk2H, g_gk2_h);
    cudaGetSymbolAddress((void**)&f1wH, g_f1w_h);
    cudaGetSymbolAddress((void**)&f2wH, g_f2w_h);

    const int SMEM_SZ = 2 * STAGE;   // 58368 B
    cudaFuncSetAttribute(mma_gemm_hf<true>,  cudaFuncAttributeMaxDynamicSharedMemorySize, SMEM_SZ);
    cudaFuncSetAttribute(mma_gemm_hf<false>, cudaFuncAttributeMaxDynamicSharedMemorySize, SMEM_SZ);
    const int STEP_SMEM = 56704 * 4; // 226816 B
    cudaFuncSetAttribute(step_loop_kernel, cudaFuncAttributeMaxDynamicSharedMemorySize, STEP_SMEM);

    // launch 0: all converts + gather (hi planes only)
    cvt_fused<<<22308, 256>>>(img, W_fc, W1, gru_k, fc1_w, fc2_w, W2, target, emb);
    // encoder (A single-term): features = relu(img @ W_fc + b_fc); fp32 + hi plane
    mma_gemm_hf<false><<<dim3(2, 64), 256, SMEM_SZ>>>(imgH, nullptr, wfcH, b_fc,
                                                      features, featH, nullptr, 8192, 256, 2048, 1, 0);
    // featw1 = features @ W1 + b1 (A single-term; contractive downstream)
    mma_gemm_hf<false><<<dim3(4, 64), 256, SMEM_SZ>>>(featH, nullptr, w1H, b1,
                                                      featw1, nullptr, nullptr, 8192, 512, 256, 0, 0);
    // embmx = embtok @ gru_k[256:] + gru_b[0] (A single-term; contractive downstream)
    mma_gemm_hf<false><<<dim3(12, 47), 256, SMEM_SZ>>>(etH, nullptr, gk2H, gru_b,
                                                       embmx, nullptr, nullptr, 6016, 1536, 256, 0, 0);
    // persistent step loop
    step_loop_kernel<<<128, 256, STEP_SMEM>>>(V, bV, b2, gru_b);
    // fc1 (A 2-term: states feed logits directly) -> f1o hi plane only
    mma_gemm_hf<true><<<dim3(4, 47), 256, SMEM_SZ>>>(stH, stL, f1wH, fc1_b,
                                                     nullptr, f1oH, nullptr, 6016, 512, 512, 0, 0);
    // fc2 (A single-term)
    mma_gemm_hf<false><<<dim3(40, 47), 256, SMEM_SZ>>>(f1oH, nullptr, f2wH, fc2_b,
                                                       out, nullptr, nullptr, 6016, 5000, 512, 0, 1);
}